// round 14
// baseline (speedup 1.0000x reference)
#include <cuda_runtime.h>
#include <math.h>
#include <stdint.h>

#define TT     128
#define BB     64
#define IDIMq  256
#define CDIMq  512
#define RRq    4
#define NNq    128
#define WWq    64
#define IFACEq 471
#define EPSq   1e-6f
#define DELTAq 5e-6f
#define CATW   768
#define NBLK   128

// ---------------- static device scratch ----------------
__device__ float g_G   [(size_t)TT * 2048 * BB];   // TRANSPOSED pre-gates [t][gate][bb]
__device__ float g_h0  [(size_t)TT * BB * CDIMq];
__device__ float g_h1  [(size_t)TT * BB * CDIMq];
__device__ float g_cat [(size_t)TT * BB * CATW];
__device__ float g_xi  [(size_t)TT * BB * IFACEq];
__device__ __align__(128) unsigned g_bar_cnt = 0;
__device__ __align__(128) unsigned g_bar_gen = 0;

__device__ __forceinline__ float sigm(float x)  { return 1.f / (1.f + expf(-x)); }
__device__ __forceinline__ float splus(float x) { return fmaxf(x, 0.f) + log1pf(expf(-fabsf(x))); }
__device__ __forceinline__ float warp_sum(float v) {
#pragma unroll
    for (int o = 16; o; o >>= 1) v += __shfl_xor_sync(0xffffffffu, v, o);
    return v;
}
__device__ __forceinline__ float warp_max(float v) {
#pragma unroll
    for (int o = 16; o; o >>= 1) v = fmaxf(v, __shfl_xor_sync(0xffffffffu, v, o));
    return v;
}

__device__ __forceinline__ void cp16(uint32_t dst, const void* src) {
    asm volatile("cp.async.cg.shared.global [%0], [%1], 16;" :: "r"(dst), "l"(src));
}
__device__ __forceinline__ void cp_commit() {
    asm volatile("cp.async.commit_group;");
}
__device__ __forceinline__ void cp_wait1() {
    asm volatile("cp.async.wait_group 1;");
}
__device__ __forceinline__ void cp_wait0() {
    asm volatile("cp.async.wait_group 0;");
}

// ---------------- tf32 helpers ----------------
__device__ __forceinline__ uint32_t f2tf32(float f) {
    uint32_t r;
    asm("cvt.rna.tf32.f32 %0, %1;" : "=r"(r) : "f"(f));
    return r;
}
__device__ __forceinline__ void mma_tf32(float* d, const uint32_t* a, uint32_t b0, uint32_t b1) {
    asm volatile(
        "mma.sync.aligned.m16n8k8.row.col.f32.tf32.tf32.f32 "
        "{%0,%1,%2,%3}, {%4,%5,%6,%7}, {%8,%9}, {%0,%1,%2,%3};"
        : "+f"(d[0]), "+f"(d[1]), "+f"(d[2]), "+f"(d[3])
        : "r"(a[0]), "r"(a[1]), "r"(a[2]), "r"(a[3]), "r"(b0), "r"(b1));
}

// ---------------- release/acquire two-phase grid barrier ----------------
__device__ __forceinline__ unsigned ld_acq(unsigned* p) {
    unsigned v;
    asm volatile("ld.acquire.gpu.global.u32 %0, [%1];" : "=r"(v) : "l"(p) : "memory");
    return v;
}
__device__ __forceinline__ unsigned atom_add_rel(unsigned* p, unsigned v) {
    unsigned old;
    asm volatile("atom.release.gpu.global.add.u32 %0, [%1], %2;"
                 : "=r"(old) : "l"(p), "r"(v) : "memory");
    return old;
}
__device__ __forceinline__ void grid_sync() {
    __syncthreads();
    if (threadIdx.x == 0) {
        unsigned gen = ld_acq(&g_bar_gen);
        unsigned arr = atom_add_rel(&g_bar_cnt, 1u);
        if (arr == NBLK - 1u) {
            atomicExch(&g_bar_cnt, 0u);
            atom_add_rel(&g_bar_gen, 1u);
        } else {
            while (ld_acq(&g_bar_gen) == gen) { }
        }
    }
    __syncthreads();
}

// ---------------- SGEMM (fp32, for xi + out): C = A @ B^T + bias ----------------
__global__ void __launch_bounds__(256) sgemm_bt(
    const float* __restrict__ A, int lda,
    const float* __restrict__ B, int ldb,
    float* __restrict__ C, int ldc,
    const float* __restrict__ bias1, const float* __restrict__ bias2,
    int N, int K)
{
    __shared__ float As[8][128];
    __shared__ float Bs[8][128];
    const int m0 = blockIdx.y * 128, n0 = blockIdx.x * 128;
    const int tid = threadIdx.x;
    const int lrow = tid >> 1;
    const int lk = (tid & 1) * 4;
    const int tx = tid & 15, ty = tid >> 4;

    float acc[8][8];
#pragma unroll
    for (int i = 0; i < 8; i++)
#pragma unroll
        for (int j = 0; j < 8; j++) acc[i][j] = 0.f;

    for (int k0 = 0; k0 < K; k0 += 8) {
        float4 av = *(const float4*)(A + (size_t)(m0 + lrow) * lda + k0 + lk);
        As[lk + 0][lrow] = av.x; As[lk + 1][lrow] = av.y;
        As[lk + 2][lrow] = av.z; As[lk + 3][lrow] = av.w;
        int nr = n0 + lrow;
        float4 bv = make_float4(0.f, 0.f, 0.f, 0.f);
        if (nr < N) bv = *(const float4*)(B + (size_t)nr * ldb + k0 + lk);
        Bs[lk + 0][lrow] = bv.x; Bs[lk + 1][lrow] = bv.y;
        Bs[lk + 2][lrow] = bv.z; Bs[lk + 3][lrow] = bv.w;
        __syncthreads();
#pragma unroll
        for (int k = 0; k < 8; k++) {
            float4 a0 = *(float4*)&As[k][ty * 8 + 0];
            float4 a1 = *(float4*)&As[k][ty * 8 + 4];
            float4 b0 = *(float4*)&Bs[k][tx * 8 + 0];
            float4 b1 = *(float4*)&Bs[k][tx * 8 + 4];
            float ar[8] = {a0.x, a0.y, a0.z, a0.w, a1.x, a1.y, a1.z, a1.w};
            float br[8] = {b0.x, b0.y, b0.z, b0.w, b1.x, b1.y, b1.z, b1.w};
#pragma unroll
            for (int i = 0; i < 8; i++)
#pragma unroll
                for (int j = 0; j < 8; j++) acc[i][j] += ar[i] * br[j];
        }
        __syncthreads();
    }
#pragma unroll
    for (int i = 0; i < 8; i++) {
        int m = m0 + ty * 8 + i;
#pragma unroll
        for (int j = 0; j < 8; j++) {
            int n = n0 + tx * 8 + j;
            if (n < N) {
                float v = acc[i][j] + bias1[n];
                if (bias2) v += bias2[n];
                C[(size_t)m * ldc + n] = v;
            }
        }
    }
}

// ---------------- TF32 tensor-core GEMM, transposed output C[t][n][bb] ----------------
#define GRAWA 0
#define GRAWB 4096
#define GAHI  8192
#define GALO  10752
#define GBHI  13312
#define GBLO  15872
#define GTS   18432
#define GSM_FLOATS 26752          // 107008 bytes

__global__ void __launch_bounds__(256) sgemm_tf32_tg(
    const float* __restrict__ A, int lda,
    const float* __restrict__ B, int ldb,
    float* __restrict__ C,
    const float* __restrict__ bias1, const float* __restrict__ bias2,
    int K)
{
    extern __shared__ float smf[];
    const int tid  = threadIdx.x;
    const int lane = tid & 31, warp = tid >> 5;
    const int g4id = lane >> 2, ctg = lane & 3;
    const int wm = warp >> 2, wn = warp & 3;
    const int m0 = blockIdx.y * 128, n0 = blockIdx.x * 128;
    const uint32_t sm_u32 = (uint32_t)__cvta_generic_to_shared(smf);

    const int nIter = K >> 4;

    auto stage = [&](int buf, int k0) {
#pragma unroll
        for (int q = 0; q < 2; q++) {
            int i = tid + q * 256;
            int row = i >> 2, c4 = (i & 3) * 4;
            cp16(sm_u32 + (uint32_t)(GRAWA + buf * 2048 + row * 16 + c4) * 4u,
                 A + (size_t)(m0 + row) * lda + k0 + c4);
            cp16(sm_u32 + (uint32_t)(GRAWB + buf * 2048 + row * 16 + c4) * 4u,
                 B + (size_t)(n0 + row) * ldb + k0 + c4);
        }
        cp_commit();
    };

    float acc[4][4][4];
#pragma unroll
    for (int mt = 0; mt < 4; mt++)
#pragma unroll
        for (int nt = 0; nt < 4; nt++)
#pragma unroll
            for (int q = 0; q < 4; q++) acc[mt][nt][q] = 0.f;

    stage(0, 0);

    for (int it = 0; it < nIter; it++) {
        const int buf = it & 1;
        if (it + 1 < nIter) {
            stage(buf ^ 1, (it + 1) * 16);
            cp_wait1();
        } else {
            cp_wait0();
        }
        __syncthreads();

#pragma unroll
        for (int q = 0; q < 2; q++) {
            int i = tid + q * 256;
            int row = i >> 2, c = (i & 3) * 4;
            float4 va = *(float4*)&smf[GRAWA + buf * 2048 + row * 16 + c];
            uint32_t h0 = f2tf32(va.x), h1 = f2tf32(va.y), h2 = f2tf32(va.z), h3 = f2tf32(va.w);
            *(float4*)&smf[GAHI + row * 20 + c] = make_float4(
                __uint_as_float(h0), __uint_as_float(h1), __uint_as_float(h2), __uint_as_float(h3));
            *(float4*)&smf[GALO + row * 20 + c] = make_float4(
                __uint_as_float(f2tf32(va.x - __uint_as_float(h0))),
                __uint_as_float(f2tf32(va.y - __uint_as_float(h1))),
                __uint_as_float(f2tf32(va.z - __uint_as_float(h2))),
                __uint_as_float(f2tf32(va.w - __uint_as_float(h3))));
            float4 vb = *(float4*)&smf[GRAWB + buf * 2048 + row * 16 + c];
            uint32_t g0 = f2tf32(vb.x), g1 = f2tf32(vb.y), g2 = f2tf32(vb.z), g3 = f2tf32(vb.w);
            *(float4*)&smf[GBHI + row * 20 + c] = make_float4(
                __uint_as_float(g0), __uint_as_float(g1), __uint_as_float(g2), __uint_as_float(g3));
            *(float4*)&smf[GBLO + row * 20 + c] = make_float4(
                __uint_as_float(f2tf32(vb.x - __uint_as_float(g0))),
                __uint_as_float(f2tf32(vb.y - __uint_as_float(g1))),
                __uint_as_float(f2tf32(vb.z - __uint_as_float(g2))),
                __uint_as_float(f2tf32(vb.w - __uint_as_float(g3))));
        }
        __syncthreads();

#pragma unroll
        for (int kt = 0; kt < 2; kt++) {
            uint32_t ahi[4][4], alo[4][4];
#pragma unroll
            for (int mt = 0; mt < 4; mt++) {
                int rb = (wm * 64 + mt * 16 + g4id) * 20 + kt * 8 + ctg;
                ahi[mt][0] = __float_as_uint(smf[GAHI + rb]);
                ahi[mt][1] = __float_as_uint(smf[GAHI + rb + 160]);
                ahi[mt][2] = __float_as_uint(smf[GAHI + rb + 4]);
                ahi[mt][3] = __float_as_uint(smf[GAHI + rb + 164]);
                alo[mt][0] = __float_as_uint(smf[GALO + rb]);
                alo[mt][1] = __float_as_uint(smf[GALO + rb + 160]);
                alo[mt][2] = __float_as_uint(smf[GALO + rb + 4]);
                alo[mt][3] = __float_as_uint(smf[GALO + rb + 164]);
            }
#pragma unroll
            for (int nt = 0; nt < 4; nt++) {
                int rb = (wn * 32 + nt * 8 + g4id) * 20 + kt * 8 + ctg;
                uint32_t bh0 = __float_as_uint(smf[GBHI + rb]);
                uint32_t bh1 = __float_as_uint(smf[GBHI + rb + 4]);
                uint32_t bl0 = __float_as_uint(smf[GBLO + rb]);
                uint32_t bl1 = __float_as_uint(smf[GBLO + rb + 4]);
#pragma unroll
                for (int mt = 0; mt < 4; mt++) {
                    mma_tf32(acc[mt][nt], ahi[mt], bh0, bh1);
                    mma_tf32(acc[mt][nt], alo[mt], bh0, bh1);
                    mma_tf32(acc[mt][nt], ahi[mt], bl0, bl1);
                }
            }
        }
    }

    float bsv[4][2];
#pragma unroll
    for (int nt = 0; nt < 4; nt++)
#pragma unroll
        for (int e = 0; e < 2; e++) {
            int n = n0 + wn * 32 + nt * 8 + ctg * 2 + e;
            bsv[nt][e] = bias1[n] + bias2[n];
        }

    const int t0 = m0 >> 6;
    __syncthreads();
#pragma unroll
    for (int h = 0; h < 2; h++) {
        if (wm == h) {
#pragma unroll
            for (int mt = 0; mt < 4; mt++)
#pragma unroll
                for (int nt = 0; nt < 4; nt++)
#pragma unroll
                    for (int q = 0; q < 4; q++) {
                        int ml = mt * 16 + g4id + (q >> 1) * 8;
                        int nl = wn * 32 + nt * 8 + ctg * 2 + (q & 1);
                        smf[GTS + nl * 65 + ml] = acc[mt][nt][q] + bsv[nt][q & 1];
                    }
        }
        __syncthreads();
        {
            float* dst = C + (size_t)(t0 + h) * 131072 + (size_t)n0 * 64;
#pragma unroll
            for (int w4 = 0; w4 < 8; w4++) {
                int f = w4 * 1024 + tid * 4;
                int nl = f >> 6, bbm = f & 63;
                float4 v;
                v.x = smf[GTS + nl * 65 + bbm + 0];
                v.y = smf[GTS + nl * 65 + bbm + 1];
                v.z = smf[GTS + nl * 65 + bbm + 2];
                v.w = smf[GTS + nl * 65 + bbm + 3];
                *(float4*)(dst + f) = v;
            }
        }
        __syncthreads();
    }
}

// ---------------- persistent LSTM layer: 16-warp 3xTF32 mma.sync matvec ----------------
// 128 blocks x 512 threads (16 warps, 4/SMSP). Warp w owns k in [32w, 32w+32)
// (4 k-tiles). A-fragments (Whh) in registers (32 regs). Reduce over 16 partials.
#define HPITCH 516
#define H_OFF  0
#define RPITCH 72
#define RWARP  (16 * RPITCH)              // 1152
#define R_OFF  33024                      // 64*516
#define G_OFF  (R_OFF + 16 * RWARP)       // 33024 + 18432 = 51456
#define HB_OFF (G_OFF + 2048)             // 53504
#define SM_FLOATS (HB_OFF + 256)          // 53760 floats = 215040 B

__global__ void __launch_bounds__(512, 1) lstm_persist(
    const float* __restrict__ Gt,        // [TT][2048][64] transposed pre-gates
    const float* __restrict__ Whh,       // [2048][512]
    float*       hhist,                  // [TT][BB][512]
    float*       clipout)                // null or g_cat base
{
    extern __shared__ float sm[];
    float* Hsm  = sm + H_OFF;
    float* Rsm  = sm + R_OFF;
    float* Gsm  = sm + G_OFF;
    float* Hbuf = sm + HB_OFF;

    const int tid = threadIdx.x, bid = blockIdx.x;
    const int warp = tid >> 5, lane = tid & 31;
    const int g4id = lane >> 2;          // 0..7
    const int ctg  = lane & 3;           // 0..3
    const int kb   = warp * 32;          // this warp's k-chunk
    const uint32_t sm_u32  = (uint32_t)__cvta_generic_to_shared(sm);
    const uint32_t hsm_u32 = sm_u32 + H_OFF * 4;
    const uint32_t gsm_u32 = sm_u32 + G_OFF * 4;

    // ---- load + split Whh A-fragments once (16 gate-rows x this warp's 32 k) ----
    uint32_t aHi[4][4], aLo[4][4];
    {
        const int rlo = g4id, rhi = g4id + 8;
        const size_t rowlo = (size_t)((rlo >> 2) * 512 + bid * 4 + (rlo & 3)) * 512;
        const size_t rowhi = (size_t)((rhi >> 2) * 512 + bid * 4 + (rhi & 3)) * 512;
#pragma unroll
        for (int kt = 0; kt < 4; kt++) {
            const int k0 = kb + kt * 8 + ctg;
            float w[4];
            w[0] = Whh[rowlo + k0];
            w[1] = Whh[rowhi + k0];
            w[2] = Whh[rowlo + k0 + 4];
            w[3] = Whh[rowhi + k0 + 4];
#pragma unroll
            for (int q = 0; q < 4; q++) {
                uint32_t hi = f2tf32(w[q]);
                aHi[kt][q] = hi;
                aLo[kt][q] = f2tf32(w[q] - __uint_as_float(hi));
            }
        }
    }

    // prefetch G slice for t=0 (4KB slice; 256 cp16 by tid<256)
    if (tid < 256) {
        const float* src = Gt + (size_t)(tid >> 6) * 32768 + bid * 256 + (tid & 63) * 4;
        cp16(gsm_u32 + tid * 16, src);
    }
    cp_commit();

    const int jl = tid >> 6;        // valid for tid<256
    const int bb = tid & 63;
    float c = 0.f;

    for (int t = 0; t < TT; t++) {
        // ---- stage h(t-1) into smem ----
        if (t == 0) {
            for (int idx = tid; idx < 64 * 128; idx += 512) {
                int b = idx >> 7, kq = idx & 127;
                *(float4*)&Hsm[b * HPITCH + kq * 4] = make_float4(0.f, 0.f, 0.f, 0.f);
            }
        } else {
            const float4* hsrc = (const float4*)(hhist + (size_t)(t - 1) * BB * 512);
#pragma unroll
            for (int ii = 0; ii < 16; ii++) {
                int idx = tid + ii * 512;
                int b = idx >> 7, kq = idx & 127;
                cp16(hsm_u32 + (uint32_t)(b * HPITCH + kq * 4) * 4u,
                     hsrc + b * 128 + kq);
            }
        }
        cp_commit();                               // group B_t
        if (t + 1 < TT && tid < 256) {             // prefetch G slice for t+1
            const float* src = Gt + (size_t)(t + 1) * 131072
                             + (size_t)(tid >> 6) * 32768 + bid * 256 + (tid & 63) * 4;
            cp16(gsm_u32 + (uint32_t)(((t + 1) & 1) * 4096) + tid * 16, src);
        }
        cp_commit();                               // group C_t
        cp_wait1();                                // B_t + C_{t-1} done
        __syncthreads();

        // ---- tensor-core matvec: 4 k-tiles x 8 n-tiles, 3xTF32 ----
        float d[8][4];
#pragma unroll
        for (int nt = 0; nt < 8; nt++)
#pragma unroll
            for (int q = 0; q < 4; q++) d[nt][q] = 0.f;

#pragma unroll
        for (int kt = 0; kt < 4; kt++) {
            const int kcol = kb + kt * 8 + ctg;
#pragma unroll
            for (int nt = 0; nt < 8; nt++) {
                const float* hp = Hsm + (nt * 8 + g4id) * HPITCH + kcol;
                float b0f = hp[0];
                float b1f = hp[4];
                uint32_t h0 = f2tf32(b0f);
                uint32_t h1 = f2tf32(b1f);
                uint32_t l0 = f2tf32(b0f - __uint_as_float(h0));
                uint32_t l1 = f2tf32(b1f - __uint_as_float(h1));
                mma_tf32(d[nt], aHi[kt], h0, h1);
                mma_tf32(d[nt], aLo[kt], h0, h1);
                mma_tf32(d[nt], aHi[kt], l0, l1);
            }
        }

        // ---- write warp partials to Rsm ----
        {
            float* rw = Rsm + warp * RWARP;
#pragma unroll
            for (int nt = 0; nt < 8; nt++) {
                int col = nt * 8 + ctg * 2;
                *(float2*)&rw[g4id * RPITCH + col]       = make_float2(d[nt][0], d[nt][1]);
                *(float2*)&rw[(g4id + 8) * RPITCH + col] = make_float2(d[nt][2], d[nt][3]);
            }
        }
        __syncthreads();

        // ---- gate math (tid<256): sum 16 partials + Gpre, update c,h ----
        if (tid < 256) {
            const float* gs = Gsm + (t & 1) * 1024;
            float g4[4];
#pragma unroll
            for (int g = 0; g < 4; g++) {
                int r = g * 4 + jl;
                float s = 0.f;
#pragma unroll
                for (int p = 0; p < 16; p++) s += Rsm[p * RWARP + r * RPITCH + bb];
                g4[g] = s + gs[g * 256 + tid];
            }
            c = sigm(g4[1]) * c + sigm(g4[0]) * tanhf(g4[2]);
            float h = sigm(g4[3]) * tanhf(c);
            Hbuf[bb * 4 + jl] = h;
        }
        __syncthreads();

        // ---- gathered coalesced store: 64 threads emit STG.128 ----
        if (tid < 64) {
            float4 v = *(float4*)&Hbuf[tid * 4];
            *(float4*)&hhist[(size_t)t * BB * 512 + (size_t)tid * 512 + bid * 4] = v;
            if (clipout) {
                float4 cv;
                cv.x = fminf(fmaxf(v.x, -20.f), 20.f);
                cv.y = fminf(fmaxf(v.y, -20.f), 20.f);
                cv.z = fminf(fmaxf(v.z, -20.f), 20.f);
                cv.w = fminf(fmaxf(v.w, -20.f), 20.f);
                *(float4*)&clipout[((size_t)t * BB + tid) * CATW + bid * 4] = cv;
            }
        }

        if (t + 1 < TT) grid_sync();
    }
}

// ---------------- DNC memory module (unchanged) ----------------
struct MemSmem {
    float mem[NNq][WWq + 1];
    float link[NNq][NNq + 1];
    float prec[NNq], usage[NNq], ww[NNq];
    float rw[RRq][NNq], rw2[RRq][NNq], fwd[RRq][NNq], bwd[RRq][NNq], rc[RRq][NNq];
    float wc[NNq], u[NNq], su[NNq], pe[NNq], norms[NNq];
    int   rank[NNq];
    float rkeys[RRq][WWq];
    float wkey[WWq], wvec[WWq], erase[WWq];
    float rstr[RRq], fg[RRq], rknorm[RRq];
    float modes[RRq][3];
    float scal[8];
};
#define S_WSTR 0
#define S_AG   1
#define S_WG   2
#define S_KN   3
#define S_SWW  4

__global__ void __launch_bounds__(256) memory_kernel(
    const float* __restrict__ xi_all, float* __restrict__ cat)
{
    extern __shared__ __align__(16) char smraw[];
    MemSmem* s = (MemSmem*)smraw;
    const int b = blockIdx.x, tid = threadIdx.x;

    for (int i = tid; i < (int)(sizeof(MemSmem) / 4); i += 256) ((float*)smraw)[i] = 0.f;
    __syncthreads();

    for (int t = 0; t < TT; t++) {
        const float* xi = xi_all + ((size_t)t * BB + b) * IFACEq;

        { int r = tid >> 6, w = tid & 63; s->rkeys[r][w] = tanhf(xi[tid]); }
        if (tid < 64) {
            s->wkey[tid]  = tanhf(xi[260 + tid]);
            s->erase[tid] = sigm (xi[325 + tid]);
            s->wvec[tid]  = tanhf(xi[389 + tid]);
        } else if (tid < 68) s->rstr[tid - 64] = splus(xi[256 + tid - 64]);
        else if (tid < 72)   s->fg[tid - 68]   = sigm (xi[453 + tid - 68]);
        else if (tid == 72)  s->scal[S_WSTR]   = splus(xi[324]);
        else if (tid == 73)  s->scal[S_AG]     = sigm (xi[457]);
        else if (tid == 74)  s->scal[S_WG]     = sigm (xi[458]);
        else if (tid >= 80 && tid < 84) {
            int r = tid - 80;
            float x0 = xi[459 + 3*r], x1 = xi[460 + 3*r], x2 = xi[461 + 3*r];
            float m = fmaxf(x0, fmaxf(x1, x2));
            float e0 = expf(x0 - m), e1 = expf(x1 - m), e2 = expf(x2 - m);
            float inv = 1.f / (e0 + e1 + e2);
            s->modes[r][0] = e0*inv; s->modes[r][1] = e1*inv; s->modes[r][2] = e2*inv;
        }
        __syncthreads();

        if (tid < 128) {
            float us = s->usage[tid] + (1.f - s->usage[tid]) * s->ww[tid];
            float ret = 1.f;
#pragma unroll
            for (int r = 0; r < RRq; r++) ret *= (1.f - s->fg[r] * s->rw[r][tid]);
            s->usage[tid] = us * ret;
            float ss = 0.f;
#pragma unroll 8
            for (int w = 0; w < WWq; w++) { float v = s->mem[tid][w]; ss += v * v; }
            s->norms[tid] = sqrtf(ss);
        } else if (tid < 160) {
            int l = tid - 128;
            float pq = s->wkey[l]*s->wkey[l] + s->wkey[l+32]*s->wkey[l+32];
            pq = warp_sum(pq);
            if (l == 0) s->scal[S_KN] = sqrtf(pq);
        } else if (tid < 164) {
            int r = tid - 160; float ss = 0.f;
            for (int w = 0; w < WWq; w++) ss += s->rkeys[r][w]*s->rkeys[r][w];
            s->rknorm[r] = sqrtf(ss);
        }
        __syncthreads();

        if (tid < 128) {
            float d = 0.f;
#pragma unroll 8
            for (int w = 0; w < WWq; w++) d += s->wkey[w] * s->mem[tid][w];
            s->wc[tid] = d / ((s->norms[tid] + EPSq) * (s->scal[S_KN] + EPSq)) * s->scal[S_WSTR];
        }
        __syncthreads();
        if (tid < 32) {
            float v0 = s->wc[tid], v1 = s->wc[tid+32], v2 = s->wc[tid+64], v3 = s->wc[tid+96];
            float mx = warp_max(fmaxf(fmaxf(v0, v1), fmaxf(v2, v3)));
            v0 = expf(v0-mx); v1 = expf(v1-mx); v2 = expf(v2-mx); v3 = expf(v3-mx);
            float inv = 1.f / warp_sum(v0 + v1 + v2 + v3);
            s->wc[tid] = v0*inv; s->wc[tid+32] = v1*inv; s->wc[tid+64] = v2*inv; s->wc[tid+96] = v3*inv;
        }
        __syncthreads();

        if (tid < 128) s->u[tid] = DELTAq + (1.f - DELTAq) * s->usage[tid];
        __syncthreads();
        if (tid < 128) {
            float ui = s->u[tid]; int rk = 0;
            for (int j = 0; j < 128; j++) {
                float uj = s->u[j];
                rk += (uj < ui) || (uj == ui && j < tid);
            }
            s->rank[tid] = rk;
            s->su[rk] = ui;
        }
        __syncthreads();
        if (tid < 128) s->pe[tid] = s->su[tid];
        __syncthreads();
        for (int d = 1; d < 128; d <<= 1) {
            float v = 1.f;
            if (tid < 128 && tid >= d) v = s->pe[tid - d];
            __syncthreads();
            if (tid < 128 && tid >= d) s->pe[tid] *= v;
            __syncthreads();
        }
        if (tid < 128) {
            int rk = s->rank[tid];
            float excl = rk ? s->pe[rk - 1] : 1.f;
            float alloc = (1.f - s->u[tid]) * excl;
            float ag = s->scal[S_AG], wg = s->scal[S_WG];
            s->ww[tid] = wg * (ag * alloc + (1.f - ag) * s->wc[tid]);
        }
        __syncthreads();
        if (tid < 32) {
            float v = s->ww[tid] + s->ww[tid+32] + s->ww[tid+64] + s->ww[tid+96];
            v = warp_sum(v);
            if (tid == 0) s->scal[S_SWW] = v;
        }
        __syncthreads();

        {
            int w = tid & 63, ng = tid >> 6;
            for (int i = 0; i < 32; i++) {
                int n = ng * 32 + i;
                float wwn = s->ww[n];
                s->mem[n][w] = s->mem[n][w] * (1.f - wwn * s->erase[w]) + wwn * s->wvec[w];
            }
        }
        {
            int i = tid >> 1, j0 = (tid & 1) * 64;
            float wwi = s->ww[i];
            for (int jj = 0; jj < 64; jj++) {
                int j = j0 + jj;
                float l = (1.f - wwi - s->ww[j]) * s->link[i][j] + wwi * s->prec[j];
                s->link[i][j] = (i == j) ? 0.f : l;
            }
        }
        __syncthreads();
        if (tid < 128) {
            s->prec[tid] = (1.f - s->scal[S_SWW]) * s->prec[tid] + s->ww[tid];
            float ss = 0.f;
#pragma unroll 8
            for (int w = 0; w < WWq; w++) { float v = s->mem[tid][w]; ss += v * v; }
            s->norms[tid] = sqrtf(ss);
        }
        __syncthreads();

        for (int q = tid; q < 512; q += 256) {
            int r = q >> 7, n = q & 127;
            float d = 0.f;
#pragma unroll 8
            for (int w = 0; w < WWq; w++) d += s->rkeys[r][w] * s->mem[n][w];
            s->rc[r][n] = d / ((s->norms[n] + EPSq) * (s->rknorm[r] + EPSq)) * s->rstr[r];
        }
        __syncthreads();
        if (tid < 128) {
            int r = tid >> 5, l = tid & 31;
            float v0 = s->rc[r][l], v1 = s->rc[r][l+32], v2 = s->rc[r][l+64], v3 = s->rc[r][l+96];
            float mx = warp_max(fmaxf(fmaxf(v0, v1), fmaxf(v2, v3)));
            v0 = expf(v0-mx); v1 = expf(v1-mx); v2 = expf(v2-mx); v3 = expf(v3-mx);
            float inv = 1.f / warp_sum(v0 + v1 + v2 + v3);
            s->rc[r][l] = v0*inv; s->rc[r][l+32] = v1*inv; s->rc[r][l+64] = v2*inv; s->rc[r][l+96] = v3*inv;
        }
        __syncthreads();

        for (int q = tid; q < 512; q += 256) {
            int r = q >> 7, n = q & 127;
            float f = 0.f, bw = 0.f;
#pragma unroll 4
            for (int m = 0; m < 128; m++) {
                float rv = s->rw[r][m];
                f  += rv * s->link[n][m];
                bw += rv * s->link[m][n];
            }
            s->fwd[r][n] = f; s->bwd[r][n] = bw;
        }
        __syncthreads();
        for (int q = tid; q < 512; q += 256) {
            int r = q >> 7, n = q & 127;
            s->rw2[r][n] = s->modes[r][0]*s->bwd[r][n] + s->modes[r][1]*s->rc[r][n] + s->modes[r][2]*s->fwd[r][n];
        }
        __syncthreads();
        for (int q = tid; q < 512; q += 256) { int r = q >> 7, n = q & 127; s->rw[r][n] = s->rw2[r][n]; }
        __syncthreads();

        {
            int r = tid >> 6, w = tid & 63;
            float acc = 0.f;
#pragma unroll 4
            for (int n = 0; n < 128; n++) acc += s->rw[r][n] * s->mem[n][w];
            cat[((size_t)t * BB + b) * CATW + 512 + tid] = acc;
        }
        __syncthreads();
    }
}

__global__ void gather_hid(float* __restrict__ out, const int* __restrict__ lens) {
    int b = blockIdx.x, i = threadIdx.x;
    int t = lens[b] - 1;
    out[(size_t)TT * BB * IDIMq + (size_t)b * IDIMq + i] = out[((size_t)t * BB + b) * IDIMq + i];
}

extern "C" void kernel_launch(void* const* d_in, const int* in_sizes, int n_in,
                              void* d_out, int out_size) {
    const float* embs = (const float*)d_in[0];
    const int*   lens = (const int*)  d_in[1];
    const float* Wih0 = (const float*)d_in[2];
    const float* Whh0 = (const float*)d_in[3];
    const float* bih0 = (const float*)d_in[4];
    const float* bhh0 = (const float*)d_in[5];
    const float* Wih1 = (const float*)d_in[6];
    const float* Whh1 = (const float*)d_in[7];
    const float* bih1 = (const float*)d_in[8];
    const float* bhh1 = (const float*)d_in[9];
    const float* Wxi  = (const float*)d_in[10];
    const float* bxi  = (const float*)d_in[11];
    const float* Wout = (const float*)d_in[12];
    const float* bout = (const float*)d_in[13];
    float* out = (float*)d_out;

    float *G, *h0, *h1, *cat, *xi;
    cudaGetSymbolAddress((void**)&G,   g_G);
    cudaGetSymbolAddress((void**)&h0,  g_h0);
    cudaGetSymbolAddress((void**)&h1,  g_h1);
    cudaGetSymbolAddress((void**)&cat, g_cat);
    cudaGetSymbolAddress((void**)&xi,  g_xi);

    cudaFuncSetAttribute(memory_kernel, cudaFuncAttributeMaxDynamicSharedMemorySize,
                         (int)sizeof(MemSmem));
    cudaFuncSetAttribute(lstm_persist, cudaFuncAttributeMaxDynamicSharedMemorySize,
                         SM_FLOATS * 4);
    cudaFuncSetAttribute(sgemm_tf32_tg, cudaFuncAttributeMaxDynamicSharedMemorySize,
                         GSM_FLOATS * 4);

    // Gpre0^T = (embs @ Wih0[:, :256]^T + bih0 + bhh0) transposed  [t][2048][64]
    sgemm_tf32_tg<<<dim3(16, 64), 256, GSM_FLOATS * 4>>>(embs, IDIMq, Wih0, CDIMq, G, bih0, bhh0, IDIMq);

    // layer 0: all 128 steps, one persistent kernel
    lstm_persist<<<NBLK, 512, SM_FLOATS * 4>>>(G, Whh0, h0, nullptr);

    // Gpre1^T = (h0 @ Wih1^T + bih1 + bhh1) transposed
    sgemm_tf32_tg<<<dim3(16, 64), 256, GSM_FLOATS * 4>>>(h0, CDIMq, Wih1, CDIMq, G, bih1, bhh1, CDIMq);

    // layer 1: all 128 steps (also writes clip(h1) into cat)
    lstm_persist<<<NBLK, 512, SM_FLOATS * 4>>>(G, Whh1, h1, cat);

    // xi = clip(h1) @ Wxi^T + bxi
    sgemm_bt<<<dim3(4, 64), 256>>>(cat, CATW, Wxi, CDIMq, xi, IFACEq, bxi, nullptr, IFACEq, CDIMq);

    memory_kernel<<<64, 256, sizeof(MemSmem)>>>(xi, cat);

    // y = cat @ Wout^T + bout
    sgemm_bt<<<dim3(2, 64), 256>>>(cat, CATW, Wout, CATW, out, IDIMq, bout, nullptr, IDIMq, CATW);

    gather_hid<<<64, 256>>>(out, lens);
}

// round 15
// speedup vs baseline: 1.0379x; 1.0379x over previous
#include <cuda_runtime.h>
#include <math.h>
#include <stdint.h>

#define TT     128
#define BB     64
#define IDIMq  256
#define CDIMq  512
#define RRq    4
#define NNq    128
#define WWq    64
#define IFACEq 471
#define EPSq   1e-6f
#define DELTAq 5e-6f
#define CATW   768
#define NBLK   128

// ---------------- static device scratch ----------------
__device__ float g_G   [(size_t)TT * 2048 * BB];   // TRANSPOSED pre-gates [t][gate][bb]
__device__ float g_h0  [(size_t)TT * BB * CDIMq];
__device__ float g_h1  [(size_t)TT * BB * CDIMq];
__device__ float g_cat [(size_t)TT * BB * CATW];
__device__ float g_xi  [(size_t)TT * BB * IFACEq];
__device__ __align__(128) unsigned g_bar_cnt = 0;
__device__ __align__(128) unsigned g_bar_gen = 0;

__device__ __forceinline__ float sigm(float x)  { return 1.f / (1.f + expf(-x)); }
__device__ __forceinline__ float splus(float x) { return fmaxf(x, 0.f) + log1pf(expf(-fabsf(x))); }
__device__ __forceinline__ float warp_sum(float v) {
#pragma unroll
    for (int o = 16; o; o >>= 1) v += __shfl_xor_sync(0xffffffffu, v, o);
    return v;
}
__device__ __forceinline__ float warp_max(float v) {
#pragma unroll
    for (int o = 16; o; o >>= 1) v = fmaxf(v, __shfl_xor_sync(0xffffffffu, v, o));
    return v;
}

__device__ __forceinline__ void cp16(uint32_t dst, const void* src) {
    asm volatile("cp.async.cg.shared.global [%0], [%1], 16;" :: "r"(dst), "l"(src));
}
__device__ __forceinline__ void cp_commit() {
    asm volatile("cp.async.commit_group;");
}
__device__ __forceinline__ void cp_wait1() {
    asm volatile("cp.async.wait_group 1;");
}
__device__ __forceinline__ void cp_wait0() {
    asm volatile("cp.async.wait_group 0;");
}

// ---------------- tf32 helpers ----------------
__device__ __forceinline__ uint32_t f2tf32(float f) {
    uint32_t r;
    asm("cvt.rna.tf32.f32 %0, %1;" : "=r"(r) : "f"(f));
    return r;
}
__device__ __forceinline__ void mma_tf32(float* d, const uint32_t* a, uint32_t b0, uint32_t b1) {
    asm volatile(
        "mma.sync.aligned.m16n8k8.row.col.f32.tf32.tf32.f32 "
        "{%0,%1,%2,%3}, {%4,%5,%6,%7}, {%8,%9}, {%0,%1,%2,%3};"
        : "+f"(d[0]), "+f"(d[1]), "+f"(d[2]), "+f"(d[3])
        : "r"(a[0]), "r"(a[1]), "r"(a[2]), "r"(a[3]), "r"(b0), "r"(b1));
}

// ---------------- release/acquire two-phase grid barrier ----------------
__device__ __forceinline__ unsigned ld_acq(unsigned* p) {
    unsigned v;
    asm volatile("ld.acquire.gpu.global.u32 %0, [%1];" : "=r"(v) : "l"(p) : "memory");
    return v;
}
__device__ __forceinline__ unsigned atom_add_rel(unsigned* p, unsigned v) {
    unsigned old;
    asm volatile("atom.release.gpu.global.add.u32 %0, [%1], %2;"
                 : "=r"(old) : "l"(p), "r"(v) : "memory");
    return old;
}
__device__ __forceinline__ void grid_sync() {
    __syncthreads();
    if (threadIdx.x == 0) {
        unsigned gen = ld_acq(&g_bar_gen);
        unsigned arr = atom_add_rel(&g_bar_cnt, 1u);
        if (arr == NBLK - 1u) {
            atomicExch(&g_bar_cnt, 0u);
            atom_add_rel(&g_bar_gen, 1u);
        } else {
            while (ld_acq(&g_bar_gen) == gen) { }
        }
    }
    __syncthreads();
}

// ---------------- TF32 GEMM mainloop macro-shared pieces ----------------
#define GRAWA 0
#define GRAWB 4096
#define GAHI  8192
#define GALO  10752
#define GBHI  13312
#define GBLO  15872
#define GTS   18432
#define GSM_FLOATS 26752          // 107008 bytes

// transposed-output variant: C[t][n][bb] (pre-gate buffer)
__global__ void __launch_bounds__(256) sgemm_tf32_tg(
    const float* __restrict__ A, int lda,
    const float* __restrict__ B, int ldb,
    float* __restrict__ C,
    const float* __restrict__ bias1, const float* __restrict__ bias2,
    int K)
{
    extern __shared__ float smf[];
    const int tid  = threadIdx.x;
    const int lane = tid & 31, warp = tid >> 5;
    const int g4id = lane >> 2, ctg = lane & 3;
    const int wm = warp >> 2, wn = warp & 3;
    const int m0 = blockIdx.y * 128, n0 = blockIdx.x * 128;
    const uint32_t sm_u32 = (uint32_t)__cvta_generic_to_shared(smf);

    const int nIter = K >> 4;

    auto stage = [&](int buf, int k0) {
#pragma unroll
        for (int q = 0; q < 2; q++) {
            int i = tid + q * 256;
            int row = i >> 2, c4 = (i & 3) * 4;
            cp16(sm_u32 + (uint32_t)(GRAWA + buf * 2048 + row * 16 + c4) * 4u,
                 A + (size_t)(m0 + row) * lda + k0 + c4);
            cp16(sm_u32 + (uint32_t)(GRAWB + buf * 2048 + row * 16 + c4) * 4u,
                 B + (size_t)(n0 + row) * ldb + k0 + c4);
        }
        cp_commit();
    };

    float acc[4][4][4];
#pragma unroll
    for (int mt = 0; mt < 4; mt++)
#pragma unroll
        for (int nt = 0; nt < 4; nt++)
#pragma unroll
            for (int q = 0; q < 4; q++) acc[mt][nt][q] = 0.f;

    stage(0, 0);

    for (int it = 0; it < nIter; it++) {
        const int buf = it & 1;
        if (it + 1 < nIter) {
            stage(buf ^ 1, (it + 1) * 16);
            cp_wait1();
        } else {
            cp_wait0();
        }
        __syncthreads();

#pragma unroll
        for (int q = 0; q < 2; q++) {
            int i = tid + q * 256;
            int row = i >> 2, c = (i & 3) * 4;
            float4 va = *(float4*)&smf[GRAWA + buf * 2048 + row * 16 + c];
            uint32_t h0 = f2tf32(va.x), h1 = f2tf32(va.y), h2 = f2tf32(va.z), h3 = f2tf32(va.w);
            *(float4*)&smf[GAHI + row * 20 + c] = make_float4(
                __uint_as_float(h0), __uint_as_float(h1), __uint_as_float(h2), __uint_as_float(h3));
            *(float4*)&smf[GALO + row * 20 + c] = make_float4(
                __uint_as_float(f2tf32(va.x - __uint_as_float(h0))),
                __uint_as_float(f2tf32(va.y - __uint_as_float(h1))),
                __uint_as_float(f2tf32(va.z - __uint_as_float(h2))),
                __uint_as_float(f2tf32(va.w - __uint_as_float(h3))));
            float4 vb = *(float4*)&smf[GRAWB + buf * 2048 + row * 16 + c];
            uint32_t g0 = f2tf32(vb.x), g1 = f2tf32(vb.y), g2 = f2tf32(vb.z), g3 = f2tf32(vb.w);
            *(float4*)&smf[GBHI + row * 20 + c] = make_float4(
                __uint_as_float(g0), __uint_as_float(g1), __uint_as_float(g2), __uint_as_float(g3));
            *(float4*)&smf[GBLO + row * 20 + c] = make_float4(
                __uint_as_float(f2tf32(vb.x - __uint_as_float(g0))),
                __uint_as_float(f2tf32(vb.y - __uint_as_float(g1))),
                __uint_as_float(f2tf32(vb.z - __uint_as_float(g2))),
                __uint_as_float(f2tf32(vb.w - __uint_as_float(g3))));
        }
        __syncthreads();

#pragma unroll
        for (int kt = 0; kt < 2; kt++) {
            uint32_t ahi[4][4], alo[4][4];
#pragma unroll
            for (int mt = 0; mt < 4; mt++) {
                int rb = (wm * 64 + mt * 16 + g4id) * 20 + kt * 8 + ctg;
                ahi[mt][0] = __float_as_uint(smf[GAHI + rb]);
                ahi[mt][1] = __float_as_uint(smf[GAHI + rb + 160]);
                ahi[mt][2] = __float_as_uint(smf[GAHI + rb + 4]);
                ahi[mt][3] = __float_as_uint(smf[GAHI + rb + 164]);
                alo[mt][0] = __float_as_uint(smf[GALO + rb]);
                alo[mt][1] = __float_as_uint(smf[GALO + rb + 160]);
                alo[mt][2] = __float_as_uint(smf[GALO + rb + 4]);
                alo[mt][3] = __float_as_uint(smf[GALO + rb + 164]);
            }
#pragma unroll
            for (int nt = 0; nt < 4; nt++) {
                int rb = (wn * 32 + nt * 8 + g4id) * 20 + kt * 8 + ctg;
                uint32_t bh0 = __float_as_uint(smf[GBHI + rb]);
                uint32_t bh1 = __float_as_uint(smf[GBHI + rb + 4]);
                uint32_t bl0 = __float_as_uint(smf[GBLO + rb]);
                uint32_t bl1 = __float_as_uint(smf[GBLO + rb + 4]);
#pragma unroll
                for (int mt = 0; mt < 4; mt++) {
                    mma_tf32(acc[mt][nt], ahi[mt], bh0, bh1);
                    mma_tf32(acc[mt][nt], alo[mt], bh0, bh1);
                    mma_tf32(acc[mt][nt], ahi[mt], bl0, bl1);
                }
            }
        }
    }

    float bsv[4][2];
#pragma unroll
    for (int nt = 0; nt < 4; nt++)
#pragma unroll
        for (int e = 0; e < 2; e++) {
            int n = n0 + wn * 32 + nt * 8 + ctg * 2 + e;
            bsv[nt][e] = bias1[n] + bias2[n];
        }

    const int t0 = m0 >> 6;
    __syncthreads();
#pragma unroll
    for (int h = 0; h < 2; h++) {
        if (wm == h) {
#pragma unroll
            for (int mt = 0; mt < 4; mt++)
#pragma unroll
                for (int nt = 0; nt < 4; nt++)
#pragma unroll
                    for (int q = 0; q < 4; q++) {
                        int ml = mt * 16 + g4id + (q >> 1) * 8;
                        int nl = wn * 32 + nt * 8 + ctg * 2 + (q & 1);
                        smf[GTS + nl * 65 + ml] = acc[mt][nt][q] + bsv[nt][q & 1];
                    }
        }
        __syncthreads();
        {
            float* dst = C + (size_t)(t0 + h) * 131072 + (size_t)n0 * 64;
#pragma unroll
            for (int w4 = 0; w4 < 8; w4++) {
                int f = w4 * 1024 + tid * 4;
                int nl = f >> 6, bbm = f & 63;
                float4 v;
                v.x = smf[GTS + nl * 65 + bbm + 0];
                v.y = smf[GTS + nl * 65 + bbm + 1];
                v.z = smf[GTS + nl * 65 + bbm + 2];
                v.w = smf[GTS + nl * 65 + bbm + 3];
                *(float4*)(dst + f) = v;
            }
        }
        __syncthreads();
    }
}

// plain-output variant: C[m][n], ragged N (row-clamped B staging, guarded stores)
__global__ void __launch_bounds__(256) sgemm_tf32_pl(
    const float* __restrict__ A, int lda,
    const float* __restrict__ B, int ldb,
    float* __restrict__ C, int ldc,
    const float* __restrict__ bias1,
    int N, int K)
{
    extern __shared__ float smf[];
    const int tid  = threadIdx.x;
    const int lane = tid & 31, warp = tid >> 5;
    const int g4id = lane >> 2, ctg = lane & 3;
    const int wm = warp >> 2, wn = warp & 3;
    const int m0 = blockIdx.y * 128, n0 = blockIdx.x * 128;
    const uint32_t sm_u32 = (uint32_t)__cvta_generic_to_shared(smf);

    const int nIter = K >> 4;

    auto stage = [&](int buf, int k0) {
#pragma unroll
        for (int q = 0; q < 2; q++) {
            int i = tid + q * 256;
            int row = i >> 2, c4 = (i & 3) * 4;
            int nr = n0 + row; if (nr > N - 1) nr = N - 1;
            cp16(sm_u32 + (uint32_t)(GRAWA + buf * 2048 + row * 16 + c4) * 4u,
                 A + (size_t)(m0 + row) * lda + k0 + c4);
            cp16(sm_u32 + (uint32_t)(GRAWB + buf * 2048 + row * 16 + c4) * 4u,
                 B + (size_t)nr * ldb + k0 + c4);
        }
        cp_commit();
    };

    float acc[4][4][4];
#pragma unroll
    for (int mt = 0; mt < 4; mt++)
#pragma unroll
        for (int nt = 0; nt < 4; nt++)
#pragma unroll
            for (int q = 0; q < 4; q++) acc[mt][nt][q] = 0.f;

    stage(0, 0);

    for (int it = 0; it < nIter; it++) {
        const int buf = it & 1;
        if (it + 1 < nIter) {
            stage(buf ^ 1, (it + 1) * 16);
            cp_wait1();
        } else {
            cp_wait0();
        }
        __syncthreads();

#pragma unroll
        for (int q = 0; q < 2; q++) {
            int i = tid + q * 256;
            int row = i >> 2, c = (i & 3) * 4;
            float4 va = *(float4*)&smf[GRAWA + buf * 2048 + row * 16 + c];
            uint32_t h0 = f2tf32(va.x), h1 = f2tf32(va.y), h2 = f2tf32(va.z), h3 = f2tf32(va.w);
            *(float4*)&smf[GAHI + row * 20 + c] = make_float4(
                __uint_as_float(h0), __uint_as_float(h1), __uint_as_float(h2), __uint_as_float(h3));
            *(float4*)&smf[GALO + row * 20 + c] = make_float4(
                __uint_as_float(f2tf32(va.x - __uint_as_float(h0))),
                __uint_as_float(f2tf32(va.y - __uint_as_float(h1))),
                __uint_as_float(f2tf32(va.z - __uint_as_float(h2))),
                __uint_as_float(f2tf32(va.w - __uint_as_float(h3))));
            float4 vb = *(float4*)&smf[GRAWB + buf * 2048 + row * 16 + c];
            uint32_t g0 = f2tf32(vb.x), g1 = f2tf32(vb.y), g2 = f2tf32(vb.z), g3 = f2tf32(vb.w);
            *(float4*)&smf[GBHI + row * 20 + c] = make_float4(
                __uint_as_float(g0), __uint_as_float(g1), __uint_as_float(g2), __uint_as_float(g3));
            *(float4*)&smf[GBLO + row * 20 + c] = make_float4(
                __uint_as_float(f2tf32(vb.x - __uint_as_float(g0))),
                __uint_as_float(f2tf32(vb.y - __uint_as_float(g1))),
                __uint_as_float(f2tf32(vb.z - __uint_as_float(g2))),
                __uint_as_float(f2tf32(vb.w - __uint_as_float(g3))));
        }
        __syncthreads();

#pragma unroll
        for (int kt = 0; kt < 2; kt++) {
            uint32_t ahi[4][4], alo[4][4];
#pragma unroll
            for (int mt = 0; mt < 4; mt++) {
                int rb = (wm * 64 + mt * 16 + g4id) * 20 + kt * 8 + ctg;
                ahi[mt][0] = __float_as_uint(smf[GAHI + rb]);
                ahi[mt][1] = __float_as_uint(smf[GAHI + rb + 160]);
                ahi[mt][2] = __float_as_uint(smf[GAHI + rb + 4]);
                ahi[mt][3] = __float_as_uint(smf[GAHI + rb + 164]);
                alo[mt][0] = __float_as_uint(smf[GALO + rb]);
                alo[mt][1] = __float_as_uint(smf[GALO + rb + 160]);
                alo[mt][2] = __float_as_uint(smf[GALO + rb + 4]);
                alo[mt][3] = __float_as_uint(smf[GALO + rb + 164]);
            }
#pragma unroll
            for (int nt = 0; nt < 4; nt++) {
                int rb = (wn * 32 + nt * 8 + g4id) * 20 + kt * 8 + ctg;
                uint32_t bh0 = __float_as_uint(smf[GBHI + rb]);
                uint32_t bh1 = __float_as_uint(smf[GBHI + rb + 4]);
                uint32_t bl0 = __float_as_uint(smf[GBLO + rb]);
                uint32_t bl1 = __float_as_uint(smf[GBLO + rb + 4]);
#pragma unroll
                for (int mt = 0; mt < 4; mt++) {
                    mma_tf32(acc[mt][nt], ahi[mt], bh0, bh1);
                    mma_tf32(acc[mt][nt], alo[mt], bh0, bh1);
                    mma_tf32(acc[mt][nt], ahi[mt], bl0, bl1);
                }
            }
        }
    }

    // direct guarded stores (no transpose)
#pragma unroll
    for (int mt = 0; mt < 4; mt++)
#pragma unroll
        for (int nt = 0; nt < 4; nt++)
#pragma unroll
            for (int q = 0; q < 4; q++) {
                int m = m0 + wm * 64 + mt * 16 + g4id + (q >> 1) * 8;
                int n = n0 + wn * 32 + nt * 8 + ctg * 2 + (q & 1);
                if (n < N)
                    C[(size_t)m * ldc + n] = acc[mt][nt][q] + bias1[n];
            }
}

// ---------------- persistent LSTM layer: 8-warp 3xTF32 mma.sync matvec (R13 best) ----------------
#define HPITCH 516
#define H_OFF  0
#define RPITCH 72
#define RWARP  (16 * RPITCH)
#define R_OFF  33024
#define G_OFF  (R_OFF + 8 * RWARP)
#define HB_OFF (G_OFF + 2048)
#define SM_FLOATS (HB_OFF + 256)

__global__ void __launch_bounds__(256, 1) lstm_persist(
    const float* __restrict__ Gt,
    const float* __restrict__ Whh,
    float*       hhist,
    float*       clipout)
{
    extern __shared__ float sm[];
    float* Hsm  = sm + H_OFF;
    float* Rsm  = sm + R_OFF;
    float* Gsm  = sm + G_OFF;
    float* Hbuf = sm + HB_OFF;

    const int tid = threadIdx.x, bid = blockIdx.x;
    const int warp = tid >> 5, lane = tid & 31;
    const int g4id = lane >> 2;
    const int ctg  = lane & 3;
    const int kb   = warp * 64;
    const uint32_t sm_u32  = (uint32_t)__cvta_generic_to_shared(sm);
    const uint32_t hsm_u32 = sm_u32 + H_OFF * 4;
    const uint32_t gsm_u32 = sm_u32 + G_OFF * 4;

    uint32_t aHi[8][4], aLo[8][4];
    {
        const int rlo = g4id, rhi = g4id + 8;
        const size_t rowlo = (size_t)((rlo >> 2) * 512 + bid * 4 + (rlo & 3)) * 512;
        const size_t rowhi = (size_t)((rhi >> 2) * 512 + bid * 4 + (rhi & 3)) * 512;
#pragma unroll
        for (int kt = 0; kt < 8; kt++) {
            const int k0 = kb + kt * 8 + ctg;
            float w[4];
            w[0] = Whh[rowlo + k0];
            w[1] = Whh[rowhi + k0];
            w[2] = Whh[rowlo + k0 + 4];
            w[3] = Whh[rowhi + k0 + 4];
#pragma unroll
            for (int q = 0; q < 4; q++) {
                uint32_t hi = f2tf32(w[q]);
                aHi[kt][q] = hi;
                aLo[kt][q] = f2tf32(w[q] - __uint_as_float(hi));
            }
        }
    }

    {
        const float* src = Gt + (size_t)(tid >> 6) * 32768 + bid * 256 + (tid & 63) * 4;
        cp16(gsm_u32 + tid * 16, src);
        cp_commit();
    }

    const int jl = tid >> 6;
    const int bb = tid & 63;
    float c = 0.f;

    for (int t = 0; t < TT; t++) {
        if (t == 0) {
            for (int idx = tid; idx < 64 * 128; idx += 256) {
                int b = idx >> 7, kq = idx & 127;
                *(float4*)&Hsm[b * HPITCH + kq * 4] = make_float4(0.f, 0.f, 0.f, 0.f);
            }
        } else {
            const float4* hsrc = (const float4*)(hhist + (size_t)(t - 1) * BB * 512);
#pragma unroll
            for (int ii = 0; ii < 32; ii++) {
                int idx = tid + ii * 256;
                int b = idx >> 7, kq = idx & 127;
                cp16(hsm_u32 + (uint32_t)(b * HPITCH + kq * 4) * 4u,
                     hsrc + b * 128 + kq);
            }
        }
        cp_commit();
        if (t + 1 < TT) {
            const float* src = Gt + (size_t)(t + 1) * 131072
                             + (size_t)(tid >> 6) * 32768 + bid * 256 + (tid & 63) * 4;
            cp16(gsm_u32 + (uint32_t)(((t + 1) & 1) * 4096) + tid * 16, src);
        }
        cp_commit();
        cp_wait1();
        __syncthreads();

        float d[8][4];
#pragma unroll
        for (int nt = 0; nt < 8; nt++)
#pragma unroll
            for (int q = 0; q < 4; q++) d[nt][q] = 0.f;

#pragma unroll
        for (int kt = 0; kt < 8; kt++) {
            const int kcol = kb + kt * 8 + ctg;
#pragma unroll
            for (int nt = 0; nt < 8; nt++) {
                const float* hp = Hsm + (nt * 8 + g4id) * HPITCH + kcol;
                float b0f = hp[0];
                float b1f = hp[4];
                uint32_t h0 = f2tf32(b0f);
                uint32_t h1 = f2tf32(b1f);
                uint32_t l0 = f2tf32(b0f - __uint_as_float(h0));
                uint32_t l1 = f2tf32(b1f - __uint_as_float(h1));
                mma_tf32(d[nt], aHi[kt], h0, h1);
                mma_tf32(d[nt], aLo[kt], h0, h1);
                mma_tf32(d[nt], aHi[kt], l0, l1);
            }
        }

        {
            float* rw = Rsm + warp * RWARP;
#pragma unroll
            for (int nt = 0; nt < 8; nt++) {
                int col = nt * 8 + ctg * 2;
                *(float2*)&rw[g4id * RPITCH + col]       = make_float2(d[nt][0], d[nt][1]);
                *(float2*)&rw[(g4id + 8) * RPITCH + col] = make_float2(d[nt][2], d[nt][3]);
            }
        }
        __syncthreads();

        {
            const float* gs = Gsm + (t & 1) * 1024;
            float g4[4];
#pragma unroll
            for (int g = 0; g < 4; g++) {
                int r = g * 4 + jl;
                float s = 0.f;
#pragma unroll
                for (int p = 0; p < 8; p++) s += Rsm[p * RWARP + r * RPITCH + bb];
                g4[g] = s + gs[g * 256 + tid];
            }
            c = sigm(g4[1]) * c + sigm(g4[0]) * tanhf(g4[2]);
            float h = sigm(g4[3]) * tanhf(c);
            Hbuf[bb * 4 + jl] = h;
        }
        __syncthreads();

        if (tid < 64) {
            float4 v = *(float4*)&Hbuf[tid * 4];
            *(float4*)&hhist[(size_t)t * BB * 512 + (size_t)tid * 512 + bid * 4] = v;
            if (clipout) {
                float4 cv;
                cv.x = fminf(fmaxf(v.x, -20.f), 20.f);
                cv.y = fminf(fmaxf(v.y, -20.f), 20.f);
                cv.z = fminf(fmaxf(v.z, -20.f), 20.f);
                cv.w = fminf(fmaxf(v.w, -20.f), 20.f);
                *(float4*)&clipout[((size_t)t * BB + tid) * CATW + bid * 4] = cv;
            }
        }

        if (t + 1 < TT) grid_sync();
    }
}

// ---------------- DNC memory module (unchanged) ----------------
struct MemSmem {
    float mem[NNq][WWq + 1];
    float link[NNq][NNq + 1];
    float prec[NNq], usage[NNq], ww[NNq];
    float rw[RRq][NNq], rw2[RRq][NNq], fwd[RRq][NNq], bwd[RRq][NNq], rc[RRq][NNq];
    float wc[NNq], u[NNq], su[NNq], pe[NNq], norms[NNq];
    int   rank[NNq];
    float rkeys[RRq][WWq];
    float wkey[WWq], wvec[WWq], erase[WWq];
    float rstr[RRq], fg[RRq], rknorm[RRq];
    float modes[RRq][3];
    float scal[8];
};
#define S_WSTR 0
#define S_AG   1
#define S_WG   2
#define S_KN   3
#define S_SWW  4

__global__ void __launch_bounds__(256) memory_kernel(
    const float* __restrict__ xi_all, float* __restrict__ cat)
{
    extern __shared__ __align__(16) char smraw[];
    MemSmem* s = (MemSmem*)smraw;
    const int b = blockIdx.x, tid = threadIdx.x;

    for (int i = tid; i < (int)(sizeof(MemSmem) / 4); i += 256) ((float*)smraw)[i] = 0.f;
    __syncthreads();

    for (int t = 0; t < TT; t++) {
        const float* xi = xi_all + ((size_t)t * BB + b) * IFACEq;

        { int r = tid >> 6, w = tid & 63; s->rkeys[r][w] = tanhf(xi[tid]); }
        if (tid < 64) {
            s->wkey[tid]  = tanhf(xi[260 + tid]);
            s->erase[tid] = sigm (xi[325 + tid]);
            s->wvec[tid]  = tanhf(xi[389 + tid]);
        } else if (tid < 68) s->rstr[tid - 64] = splus(xi[256 + tid - 64]);
        else if (tid < 72)   s->fg[tid - 68]   = sigm (xi[453 + tid - 68]);
        else if (tid == 72)  s->scal[S_WSTR]   = splus(xi[324]);
        else if (tid == 73)  s->scal[S_AG]     = sigm (xi[457]);
        else if (tid == 74)  s->scal[S_WG]     = sigm (xi[458]);
        else if (tid >= 80 && tid < 84) {
            int r = tid - 80;
            float x0 = xi[459 + 3*r], x1 = xi[460 + 3*r], x2 = xi[461 + 3*r];
            float m = fmaxf(x0, fmaxf(x1, x2));
            float e0 = expf(x0 - m), e1 = expf(x1 - m), e2 = expf(x2 - m);
            float inv = 1.f / (e0 + e1 + e2);
            s->modes[r][0] = e0*inv; s->modes[r][1] = e1*inv; s->modes[r][2] = e2*inv;
        }
        __syncthreads();

        if (tid < 128) {
            float us = s->usage[tid] + (1.f - s->usage[tid]) * s->ww[tid];
            float ret = 1.f;
#pragma unroll
            for (int r = 0; r < RRq; r++) ret *= (1.f - s->fg[r] * s->rw[r][tid]);
            s->usage[tid] = us * ret;
            float ss = 0.f;
#pragma unroll 8
            for (int w = 0; w < WWq; w++) { float v = s->mem[tid][w]; ss += v * v; }
            s->norms[tid] = sqrtf(ss);
        } else if (tid < 160) {
            int l = tid - 128;
            float pq = s->wkey[l]*s->wkey[l] + s->wkey[l+32]*s->wkey[l+32];
            pq = warp_sum(pq);
            if (l == 0) s->scal[S_KN] = sqrtf(pq);
        } else if (tid < 164) {
            int r = tid - 160; float ss = 0.f;
            for (int w = 0; w < WWq; w++) ss += s->rkeys[r][w]*s->rkeys[r][w];
            s->rknorm[r] = sqrtf(ss);
        }
        __syncthreads();

        if (tid < 128) {
            float d = 0.f;
#pragma unroll 8
            for (int w = 0; w < WWq; w++) d += s->wkey[w] * s->mem[tid][w];
            s->wc[tid] = d / ((s->norms[tid] + EPSq) * (s->scal[S_KN] + EPSq)) * s->scal[S_WSTR];
        }
        __syncthreads();
        if (tid < 32) {
            float v0 = s->wc[tid], v1 = s->wc[tid+32], v2 = s->wc[tid+64], v3 = s->wc[tid+96];
            float mx = warp_max(fmaxf(fmaxf(v0, v1), fmaxf(v2, v3)));
            v0 = expf(v0-mx); v1 = expf(v1-mx); v2 = expf(v2-mx); v3 = expf(v3-mx);
            float inv = 1.f / warp_sum(v0 + v1 + v2 + v3);
            s->wc[tid] = v0*inv; s->wc[tid+32] = v1*inv; s->wc[tid+64] = v2*inv; s->wc[tid+96] = v3*inv;
        }
        __syncthreads();

        if (tid < 128) s->u[tid] = DELTAq + (1.f - DELTAq) * s->usage[tid];
        __syncthreads();
        if (tid < 128) {
            float ui = s->u[tid]; int rk = 0;
            for (int j = 0; j < 128; j++) {
                float uj = s->u[j];
                rk += (uj < ui) || (uj == ui && j < tid);
            }
            s->rank[tid] = rk;
            s->su[rk] = ui;
        }
        __syncthreads();
        if (tid < 128) s->pe[tid] = s->su[tid];
        __syncthreads();
        for (int d = 1; d < 128; d <<= 1) {
            float v = 1.f;
            if (tid < 128 && tid >= d) v = s->pe[tid - d];
            __syncthreads();
            if (tid < 128 && tid >= d) s->pe[tid] *= v;
            __syncthreads();
        }
        if (tid < 128) {
            int rk = s->rank[tid];
            float excl = rk ? s->pe[rk - 1] : 1.f;
            float alloc = (1.f - s->u[tid]) * excl;
            float ag = s->scal[S_AG], wg = s->scal[S_WG];
            s->ww[tid] = wg * (ag * alloc + (1.f - ag) * s->wc[tid]);
        }
        __syncthreads();
        if (tid < 32) {
            float v = s->ww[tid] + s->ww[tid+32] + s->ww[tid+64] + s->ww[tid+96];
            v = warp_sum(v);
            if (tid == 0) s->scal[S_SWW] = v;
        }
        __syncthreads();

        {
            int w = tid & 63, ng = tid >> 6;
            for (int i = 0; i < 32; i++) {
                int n = ng * 32 + i;
                float wwn = s->ww[n];
                s->mem[n][w] = s->mem[n][w] * (1.f - wwn * s->erase[w]) + wwn * s->wvec[w];
            }
        }
        {
            int i = tid >> 1, j0 = (tid & 1) * 64;
            float wwi = s->ww[i];
            for (int jj = 0; jj < 64; jj++) {
                int j = j0 + jj;
                float l = (1.f - wwi - s->ww[j]) * s->link[i][j] + wwi * s->prec[j];
                s->link[i][j] = (i == j) ? 0.f : l;
            }
        }
        __syncthreads();
        if (tid < 128) {
            s->prec[tid] = (1.f - s->scal[S_SWW]) * s->prec[tid] + s->ww[tid];
            float ss = 0.f;
#pragma unroll 8
            for (int w = 0; w < WWq; w++) { float v = s->mem[tid][w]; ss += v * v; }
            s->norms[tid] = sqrtf(ss);
        }
        __syncthreads();

        for (int q = tid; q < 512; q += 256) {
            int r = q >> 7, n = q & 127;
            float d = 0.f;
#pragma unroll 8
            for (int w = 0; w < WWq; w++) d += s->rkeys[r][w] * s->mem[n][w];
            s->rc[r][n] = d / ((s->norms[n] + EPSq) * (s->rknorm[r] + EPSq)) * s->rstr[r];
        }
        __syncthreads();
        if (tid < 128) {
            int r = tid >> 5, l = tid & 31;
            float v0 = s->rc[r][l], v1 = s->rc[r][l+32], v2 = s->rc[r][l+64], v3 = s->rc[r][l+96];
            float mx = warp_max(fmaxf(fmaxf(v0, v1), fmaxf(v2, v3)));
            v0 = expf(v0-mx); v1 = expf(v1-mx); v2 = expf(v2-mx); v3 = expf(v3-mx);
            float inv = 1.f / warp_sum(v0 + v1 + v2 + v3);
            s->rc[r][l] = v0*inv; s->rc[r][l+32] = v1*inv; s->rc[r][l+64] = v2*inv; s->rc[r][l+96] = v3*inv;
        }
        __syncthreads();

        for (int q = tid; q < 512; q += 256) {
            int r = q >> 7, n = q & 127;
            float f = 0.f, bw = 0.f;
#pragma unroll 4
            for (int m = 0; m < 128; m++) {
                float rv = s->rw[r][m];
                f  += rv * s->link[n][m];
                bw += rv * s->link[m][n];
            }
            s->fwd[r][n] = f; s->bwd[r][n] = bw;
        }
        __syncthreads();
        for (int q = tid; q < 512; q += 256) {
            int r = q >> 7, n = q & 127;
            s->rw2[r][n] = s->modes[r][0]*s->bwd[r][n] + s->modes[r][1]*s->rc[r][n] + s->modes[r][2]*s->fwd[r][n];
        }
        __syncthreads();
        for (int q = tid; q < 512; q += 256) { int r = q >> 7, n = q & 127; s->rw[r][n] = s->rw2[r][n]; }
        __syncthreads();

        {
            int r = tid >> 6, w = tid & 63;
            float acc = 0.f;
#pragma unroll 4
            for (int n = 0; n < 128; n++) acc += s->rw[r][n] * s->mem[n][w];
            cat[((size_t)t * BB + b) * CATW + 512 + tid] = acc;
        }
        __syncthreads();
    }
}

__global__ void gather_hid(float* __restrict__ out, const int* __restrict__ lens) {
    int b = blockIdx.x, i = threadIdx.x;
    int t = lens[b] - 1;
    out[(size_t)TT * BB * IDIMq + (size_t)b * IDIMq + i] = out[((size_t)t * BB + b) * IDIMq + i];
}

extern "C" void kernel_launch(void* const* d_in, const int* in_sizes, int n_in,
                              void* d_out, int out_size) {
    const float* embs = (const float*)d_in[0];
    const int*   lens = (const int*)  d_in[1];
    const float* Wih0 = (const float*)d_in[2];
    const float* Whh0 = (const float*)d_in[3];
    const float* bih0 = (const float*)d_in[4];
    const float* bhh0 = (const float*)d_in[5];
    const float* Wih1 = (const float*)d_in[6];
    const float* Whh1 = (const float*)d_in[7];
    const float* bih1 = (const float*)d_in[8];
    const float* bhh1 = (const float*)d_in[9];
    const float* Wxi  = (const float*)d_in[10];
    const float* bxi  = (const float*)d_in[11];
    const float* Wout = (const float*)d_in[12];
    const float* bout = (const float*)d_in[13];
    float* out = (float*)d_out;

    float *G, *h0, *h1, *cat, *xi;
    cudaGetSymbolAddress((void**)&G,   g_G);
    cudaGetSymbolAddress((void**)&h0,  g_h0);
    cudaGetSymbolAddress((void**)&h1,  g_h1);
    cudaGetSymbolAddress((void**)&cat, g_cat);
    cudaGetSymbolAddress((void**)&xi,  g_xi);

    cudaFuncSetAttribute(memory_kernel, cudaFuncAttributeMaxDynamicSharedMemorySize,
                         (int)sizeof(MemSmem));
    cudaFuncSetAttribute(lstm_persist, cudaFuncAttributeMaxDynamicSharedMemorySize,
                         SM_FLOATS * 4);
    cudaFuncSetAttribute(sgemm_tf32_tg, cudaFuncAttributeMaxDynamicSharedMemorySize,
                         GSM_FLOATS * 4);
    cudaFuncSetAttribute(sgemm_tf32_pl, cudaFuncAttributeMaxDynamicSharedMemorySize,
                         GSM_FLOATS * 4);

    // Gpre0^T = (embs @ Wih0[:, :256]^T + bih0 + bhh0) transposed  [t][2048][64]
    sgemm_tf32_tg<<<dim3(16, 64), 256, GSM_FLOATS * 4>>>(embs, IDIMq, Wih0, CDIMq, G, bih0, bhh0, IDIMq);

    // layer 0: all 128 steps, one persistent kernel
    lstm_persist<<<NBLK, 256, SM_FLOATS * 4>>>(G, Whh0, h0, nullptr);

    // Gpre1^T = (h0 @ Wih1^T + bih1 + bhh1) transposed
    sgemm_tf32_tg<<<dim3(16, 64), 256, GSM_FLOATS * 4>>>(h0, CDIMq, Wih1, CDIMq, G, bih1, bhh1, CDIMq);

    // layer 1: all 128 steps (also writes clip(h1) into cat)
    lstm_persist<<<NBLK, 256, SM_FLOATS * 4>>>(G, Whh1, h1, cat);

    // xi = clip(h1) @ Wxi^T + bxi   (tf32, ragged N)
    sgemm_tf32_pl<<<dim3(4, 64), 256, GSM_FLOATS * 4>>>(cat, CATW, Wxi, CDIMq, xi, IFACEq, bxi, IFACEq, CDIMq);

    memory_kernel<<<64, 256, sizeof(MemSmem)>>>(xi, cat);

    // y = cat @ Wout^T + bout   (tf32)
    sgemm_tf32_pl<<<dim3(2, 64), 256, GSM_FLOATS * 4>>>(cat, CATW, Wout, CATW, out, IDIMq, bout, IDIMq, CATW);

    gather_hid<<<64, 256>>>(out, lens);
}

// round 16
// speedup vs baseline: 1.1280x; 1.0868x over previous
#include <cuda_runtime.h>
#include <math.h>
#include <stdint.h>

#define TT     128
#define BB     64
#define IDIMq  256
#define CDIMq  512
#define RRq    4
#define NNq    128
#define WWq    64
#define IFACEq 471
#define EPSq   1e-6f
#define DELTAq 5e-6f
#define CATW   768
#define NBLK   128

// ---------------- static device scratch ----------------
__device__ float g_G   [(size_t)TT * 2048 * BB];   // TRANSPOSED pre-gates [t][gate][bb]
__device__ float g_h0  [(size_t)TT * BB * CDIMq];
__device__ float g_h1  [(size_t)TT * BB * CDIMq];
__device__ float g_cat [(size_t)TT * BB * CATW];
__device__ float g_xi  [(size_t)TT * BB * IFACEq];
__device__ __align__(128) unsigned g_bar_cnt = 0;
__device__ __align__(128) unsigned g_bar_gen = 0;

__device__ __forceinline__ float sigm(float x)  { return 1.f / (1.f + expf(-x)); }
__device__ __forceinline__ float splus(float x) { return fmaxf(x, 0.f) + log1pf(expf(-fabsf(x))); }
__device__ __forceinline__ float warp_sum(float v) {
#pragma unroll
    for (int o = 16; o; o >>= 1) v += __shfl_xor_sync(0xffffffffu, v, o);
    return v;
}
__device__ __forceinline__ float warp_max(float v) {
#pragma unroll
    for (int o = 16; o; o >>= 1) v = fmaxf(v, __shfl_xor_sync(0xffffffffu, v, o));
    return v;
}

__device__ __forceinline__ void cp16(uint32_t dst, const void* src) {
    asm volatile("cp.async.cg.shared.global [%0], [%1], 16;" :: "r"(dst), "l"(src));
}
__device__ __forceinline__ void cp_commit() {
    asm volatile("cp.async.commit_group;");
}
__device__ __forceinline__ void cp_wait1() {
    asm volatile("cp.async.wait_group 1;");
}
__device__ __forceinline__ void cp_wait0() {
    asm volatile("cp.async.wait_group 0;");
}

// ---------------- tf32 helpers ----------------
__device__ __forceinline__ uint32_t f2tf32(float f) {
    uint32_t r;
    asm("cvt.rna.tf32.f32 %0, %1;" : "=r"(r) : "f"(f));
    return r;
}
__device__ __forceinline__ void mma_tf32(float* d, const uint32_t* a, uint32_t b0, uint32_t b1) {
    asm volatile(
        "mma.sync.aligned.m16n8k8.row.col.f32.tf32.tf32.f32 "
        "{%0,%1,%2,%3}, {%4,%5,%6,%7}, {%8,%9}, {%0,%1,%2,%3};"
        : "+f"(d[0]), "+f"(d[1]), "+f"(d[2]), "+f"(d[3])
        : "r"(a[0]), "r"(a[1]), "r"(a[2]), "r"(a[3]), "r"(b0), "r"(b1));
}

// ---------------- release/acquire two-phase grid barrier ----------------
__device__ __forceinline__ unsigned ld_acq(unsigned* p) {
    unsigned v;
    asm volatile("ld.acquire.gpu.global.u32 %0, [%1];" : "=r"(v) : "l"(p) : "memory");
    return v;
}
__device__ __forceinline__ unsigned atom_add_rel(unsigned* p, unsigned v) {
    unsigned old;
    asm volatile("atom.release.gpu.global.add.u32 %0, [%1], %2;"
                 : "=r"(old) : "l"(p), "r"(v) : "memory");
    return old;
}
__device__ __forceinline__ void grid_sync() {
    __syncthreads();
    if (threadIdx.x == 0) {
        unsigned gen = ld_acq(&g_bar_gen);
        unsigned arr = atom_add_rel(&g_bar_cnt, 1u);
        if (arr == NBLK - 1u) {
            atomicExch(&g_bar_cnt, 0u);
            atom_add_rel(&g_bar_gen, 1u);
        } else {
            while (ld_acq(&g_bar_gen) == gen) { }
        }
    }
    __syncthreads();
}

// ---------------- TF32 GEMM mainloop macro-shared pieces ----------------
#define GRAWA 0
#define GRAWB 4096
#define GAHI  8192
#define GALO  10752
#define GBHI  13312
#define GBLO  15872
#define GTS   18432
#define GSM_FLOATS 26752          // 107008 bytes

// transposed-output variant: C[t][n][bb] (pre-gate buffer)
__global__ void __launch_bounds__(256) sgemm_tf32_tg(
    const float* __restrict__ A, int lda,
    const float* __restrict__ B, int ldb,
    float* __restrict__ C,
    const float* __restrict__ bias1, const float* __restrict__ bias2,
    int K)
{
    extern __shared__ float smf[];
    const int tid  = threadIdx.x;
    const int lane = tid & 31, warp = tid >> 5;
    const int g4id = lane >> 2, ctg = lane & 3;
    const int wm = warp >> 2, wn = warp & 3;
    const int m0 = blockIdx.y * 128, n0 = blockIdx.x * 128;
    const uint32_t sm_u32 = (uint32_t)__cvta_generic_to_shared(smf);

    const int nIter = K >> 4;

    auto stage = [&](int buf, int k0) {
#pragma unroll
        for (int q = 0; q < 2; q++) {
            int i = tid + q * 256;
            int row = i >> 2, c4 = (i & 3) * 4;
            cp16(sm_u32 + (uint32_t)(GRAWA + buf * 2048 + row * 16 + c4) * 4u,
                 A + (size_t)(m0 + row) * lda + k0 + c4);
            cp16(sm_u32 + (uint32_t)(GRAWB + buf * 2048 + row * 16 + c4) * 4u,
                 B + (size_t)(n0 + row) * ldb + k0 + c4);
        }
        cp_commit();
    };

    float acc[4][4][4];
#pragma unroll
    for (int mt = 0; mt < 4; mt++)
#pragma unroll
        for (int nt = 0; nt < 4; nt++)
#pragma unroll
            for (int q = 0; q < 4; q++) acc[mt][nt][q] = 0.f;

    stage(0, 0);

    for (int it = 0; it < nIter; it++) {
        const int buf = it & 1;
        if (it + 1 < nIter) {
            stage(buf ^ 1, (it + 1) * 16);
            cp_wait1();
        } else {
            cp_wait0();
        }
        __syncthreads();

#pragma unroll
        for (int q = 0; q < 2; q++) {
            int i = tid + q * 256;
            int row = i >> 2, c = (i & 3) * 4;
            float4 va = *(float4*)&smf[GRAWA + buf * 2048 + row * 16 + c];
            uint32_t h0 = f2tf32(va.x), h1 = f2tf32(va.y), h2 = f2tf32(va.z), h3 = f2tf32(va.w);
            *(float4*)&smf[GAHI + row * 20 + c] = make_float4(
                __uint_as_float(h0), __uint_as_float(h1), __uint_as_float(h2), __uint_as_float(h3));
            *(float4*)&smf[GALO + row * 20 + c] = make_float4(
                __uint_as_float(f2tf32(va.x - __uint_as_float(h0))),
                __uint_as_float(f2tf32(va.y - __uint_as_float(h1))),
                __uint_as_float(f2tf32(va.z - __uint_as_float(h2))),
                __uint_as_float(f2tf32(va.w - __uint_as_float(h3))));
            float4 vb = *(float4*)&smf[GRAWB + buf * 2048 + row * 16 + c];
            uint32_t g0 = f2tf32(vb.x), g1 = f2tf32(vb.y), g2 = f2tf32(vb.z), g3 = f2tf32(vb.w);
            *(float4*)&smf[GBHI + row * 20 + c] = make_float4(
                __uint_as_float(g0), __uint_as_float(g1), __uint_as_float(g2), __uint_as_float(g3));
            *(float4*)&smf[GBLO + row * 20 + c] = make_float4(
                __uint_as_float(f2tf32(vb.x - __uint_as_float(g0))),
                __uint_as_float(f2tf32(vb.y - __uint_as_float(g1))),
                __uint_as_float(f2tf32(vb.z - __uint_as_float(g2))),
                __uint_as_float(f2tf32(vb.w - __uint_as_float(g3))));
        }
        __syncthreads();

#pragma unroll
        for (int kt = 0; kt < 2; kt++) {
            uint32_t ahi[4][4], alo[4][4];
#pragma unroll
            for (int mt = 0; mt < 4; mt++) {
                int rb = (wm * 64 + mt * 16 + g4id) * 20 + kt * 8 + ctg;
                ahi[mt][0] = __float_as_uint(smf[GAHI + rb]);
                ahi[mt][1] = __float_as_uint(smf[GAHI + rb + 160]);
                ahi[mt][2] = __float_as_uint(smf[GAHI + rb + 4]);
                ahi[mt][3] = __float_as_uint(smf[GAHI + rb + 164]);
                alo[mt][0] = __float_as_uint(smf[GALO + rb]);
                alo[mt][1] = __float_as_uint(smf[GALO + rb + 160]);
                alo[mt][2] = __float_as_uint(smf[GALO + rb + 4]);
                alo[mt][3] = __float_as_uint(smf[GALO + rb + 164]);
            }
#pragma unroll
            for (int nt = 0; nt < 4; nt++) {
                int rb = (wn * 32 + nt * 8 + g4id) * 20 + kt * 8 + ctg;
                uint32_t bh0 = __float_as_uint(smf[GBHI + rb]);
                uint32_t bh1 = __float_as_uint(smf[GBHI + rb + 4]);
                uint32_t bl0 = __float_as_uint(smf[GBLO + rb]);
                uint32_t bl1 = __float_as_uint(smf[GBLO + rb + 4]);
#pragma unroll
                for (int mt = 0; mt < 4; mt++) {
                    mma_tf32(acc[mt][nt], ahi[mt], bh0, bh1);
                    mma_tf32(acc[mt][nt], alo[mt], bh0, bh1);
                    mma_tf32(acc[mt][nt], ahi[mt], bl0, bl1);
                }
            }
        }
    }

    float bsv[4][2];
#pragma unroll
    for (int nt = 0; nt < 4; nt++)
#pragma unroll
        for (int e = 0; e < 2; e++) {
            int n = n0 + wn * 32 + nt * 8 + ctg * 2 + e;
            bsv[nt][e] = bias1[n] + bias2[n];
        }

    const int t0 = m0 >> 6;
    __syncthreads();
#pragma unroll
    for (int h = 0; h < 2; h++) {
        if (wm == h) {
#pragma unroll
            for (int mt = 0; mt < 4; mt++)
#pragma unroll
                for (int nt = 0; nt < 4; nt++)
#pragma unroll
                    for (int q = 0; q < 4; q++) {
                        int ml = mt * 16 + g4id + (q >> 1) * 8;
                        int nl = wn * 32 + nt * 8 + ctg * 2 + (q & 1);
                        smf[GTS + nl * 65 + ml] = acc[mt][nt][q] + bsv[nt][q & 1];
                    }
        }
        __syncthreads();
        {
            float* dst = C + (size_t)(t0 + h) * 131072 + (size_t)n0 * 64;
#pragma unroll
            for (int w4 = 0; w4 < 8; w4++) {
                int f = w4 * 1024 + tid * 4;
                int nl = f >> 6, bbm = f & 63;
                float4 v;
                v.x = smf[GTS + nl * 65 + bbm + 0];
                v.y = smf[GTS + nl * 65 + bbm + 1];
                v.z = smf[GTS + nl * 65 + bbm + 2];
                v.w = smf[GTS + nl * 65 + bbm + 3];
                *(float4*)(dst + f) = v;
            }
        }
        __syncthreads();
    }
}

// plain-output variant: C[m][n], ragged N (row-clamped B staging, guarded stores)
__global__ void __launch_bounds__(256) sgemm_tf32_pl(
    const float* __restrict__ A, int lda,
    const float* __restrict__ B, int ldb,
    float* __restrict__ C, int ldc,
    const float* __restrict__ bias1,
    int N, int K)
{
    extern __shared__ float smf[];
    const int tid  = threadIdx.x;
    const int lane = tid & 31, warp = tid >> 5;
    const int g4id = lane >> 2, ctg = lane & 3;
    const int wm = warp >> 2, wn = warp & 3;
    const int m0 = blockIdx.y * 128, n0 = blockIdx.x * 128;
    const uint32_t sm_u32 = (uint32_t)__cvta_generic_to_shared(smf);

    const int nIter = K >> 4;

    auto stage = [&](int buf, int k0) {
#pragma unroll
        for (int q = 0; q < 2; q++) {
            int i = tid + q * 256;
            int row = i >> 2, c4 = (i & 3) * 4;
            int nr = n0 + row; if (nr > N - 1) nr = N - 1;
            cp16(sm_u32 + (uint32_t)(GRAWA + buf * 2048 + row * 16 + c4) * 4u,
                 A + (size_t)(m0 + row) * lda + k0 + c4);
            cp16(sm_u32 + (uint32_t)(GRAWB + buf * 2048 + row * 16 + c4) * 4u,
                 B + (size_t)nr * ldb + k0 + c4);
        }
        cp_commit();
    };

    float acc[4][4][4];
#pragma unroll
    for (int mt = 0; mt < 4; mt++)
#pragma unroll
        for (int nt = 0; nt < 4; nt++)
#pragma unroll
            for (int q = 0; q < 4; q++) acc[mt][nt][q] = 0.f;

    stage(0, 0);

    for (int it = 0; it < nIter; it++) {
        const int buf = it & 1;
        if (it + 1 < nIter) {
            stage(buf ^ 1, (it + 1) * 16);
            cp_wait1();
        } else {
            cp_wait0();
        }
        __syncthreads();

#pragma unroll
        for (int q = 0; q < 2; q++) {
            int i = tid + q * 256;
            int row = i >> 2, c = (i & 3) * 4;
            float4 va = *(float4*)&smf[GRAWA + buf * 2048 + row * 16 + c];
            uint32_t h0 = f2tf32(va.x), h1 = f2tf32(va.y), h2 = f2tf32(va.z), h3 = f2tf32(va.w);
            *(float4*)&smf[GAHI + row * 20 + c] = make_float4(
                __uint_as_float(h0), __uint_as_float(h1), __uint_as_float(h2), __uint_as_float(h3));
            *(float4*)&smf[GALO + row * 20 + c] = make_float4(
                __uint_as_float(f2tf32(va.x - __uint_as_float(h0))),
                __uint_as_float(f2tf32(va.y - __uint_as_float(h1))),
                __uint_as_float(f2tf32(va.z - __uint_as_float(h2))),
                __uint_as_float(f2tf32(va.w - __uint_as_float(h3))));
            float4 vb = *(float4*)&smf[GRAWB + buf * 2048 + row * 16 + c];
            uint32_t g0 = f2tf32(vb.x), g1 = f2tf32(vb.y), g2 = f2tf32(vb.z), g3 = f2tf32(vb.w);
            *(float4*)&smf[GBHI + row * 20 + c] = make_float4(
                __uint_as_float(g0), __uint_as_float(g1), __uint_as_float(g2), __uint_as_float(g3));
            *(float4*)&smf[GBLO + row * 20 + c] = make_float4(
                __uint_as_float(f2tf32(vb.x - __uint_as_float(g0))),
                __uint_as_float(f2tf32(vb.y - __uint_as_float(g1))),
                __uint_as_float(f2tf32(vb.z - __uint_as_float(g2))),
                __uint_as_float(f2tf32(vb.w - __uint_as_float(g3))));
        }
        __syncthreads();

#pragma unroll
        for (int kt = 0; kt < 2; kt++) {
            uint32_t ahi[4][4], alo[4][4];
#pragma unroll
            for (int mt = 0; mt < 4; mt++) {
                int rb = (wm * 64 + mt * 16 + g4id) * 20 + kt * 8 + ctg;
                ahi[mt][0] = __float_as_uint(smf[GAHI + rb]);
                ahi[mt][1] = __float_as_uint(smf[GAHI + rb + 160]);
                ahi[mt][2] = __float_as_uint(smf[GAHI + rb + 4]);
                ahi[mt][3] = __float_as_uint(smf[GAHI + rb + 164]);
                alo[mt][0] = __float_as_uint(smf[GALO + rb]);
                alo[mt][1] = __float_as_uint(smf[GALO + rb + 160]);
                alo[mt][2] = __float_as_uint(smf[GALO + rb + 4]);
                alo[mt][3] = __float_as_uint(smf[GALO + rb + 164]);
            }
#pragma unroll
            for (int nt = 0; nt < 4; nt++) {
                int rb = (wn * 32 + nt * 8 + g4id) * 20 + kt * 8 + ctg;
                uint32_t bh0 = __float_as_uint(smf[GBHI + rb]);
                uint32_t bh1 = __float_as_uint(smf[GBHI + rb + 4]);
                uint32_t bl0 = __float_as_uint(smf[GBLO + rb]);
                uint32_t bl1 = __float_as_uint(smf[GBLO + rb + 4]);
#pragma unroll
                for (int mt = 0; mt < 4; mt++) {
                    mma_tf32(acc[mt][nt], ahi[mt], bh0, bh1);
                    mma_tf32(acc[mt][nt], alo[mt], bh0, bh1);
                    mma_tf32(acc[mt][nt], ahi[mt], bl0, bl1);
                }
            }
        }
    }

#pragma unroll
    for (int mt = 0; mt < 4; mt++)
#pragma unroll
        for (int nt = 0; nt < 4; nt++)
#pragma unroll
            for (int q = 0; q < 4; q++) {
                int m = m0 + wm * 64 + mt * 16 + g4id + (q >> 1) * 8;
                int n = n0 + wn * 32 + nt * 8 + ctg * 2 + (q & 1);
                if (n < N)
                    C[(size_t)m * ldc + n] = acc[mt][nt][q] + bias1[n];
            }
}

// ---------------- persistent LSTM layer: 8-warp 3xTF32 mma.sync matvec (R13/R15 best) ----------------
#define HPITCH 516
#define H_OFF  0
#define RPITCH 72
#define RWARP  (16 * RPITCH)
#define R_OFF  33024
#define G_OFF  (R_OFF + 8 * RWARP)
#define HB_OFF (G_OFF + 2048)
#define SM_FLOATS (HB_OFF + 256)

__global__ void __launch_bounds__(256, 1) lstm_persist(
    const float* __restrict__ Gt,
    const float* __restrict__ Whh,
    float*       hhist,
    float*       clipout)
{
    extern __shared__ float sm[];
    float* Hsm  = sm + H_OFF;
    float* Rsm  = sm + R_OFF;
    float* Gsm  = sm + G_OFF;
    float* Hbuf = sm + HB_OFF;

    const int tid = threadIdx.x, bid = blockIdx.x;
    const int warp = tid >> 5, lane = tid & 31;
    const int g4id = lane >> 2;
    const int ctg  = lane & 3;
    const int kb   = warp * 64;
    const uint32_t sm_u32  = (uint32_t)__cvta_generic_to_shared(sm);
    const uint32_t hsm_u32 = sm_u32 + H_OFF * 4;
    const uint32_t gsm_u32 = sm_u32 + G_OFF * 4;

    uint32_t aHi[8][4], aLo[8][4];
    {
        const int rlo = g4id, rhi = g4id + 8;
        const size_t rowlo = (size_t)((rlo >> 2) * 512 + bid * 4 + (rlo & 3)) * 512;
        const size_t rowhi = (size_t)((rhi >> 2) * 512 + bid * 4 + (rhi & 3)) * 512;
#pragma unroll
        for (int kt = 0; kt < 8; kt++) {
            const int k0 = kb + kt * 8 + ctg;
            float w[4];
            w[0] = Whh[rowlo + k0];
            w[1] = Whh[rowhi + k0];
            w[2] = Whh[rowlo + k0 + 4];
            w[3] = Whh[rowhi + k0 + 4];
#pragma unroll
            for (int q = 0; q < 4; q++) {
                uint32_t hi = f2tf32(w[q]);
                aHi[kt][q] = hi;
                aLo[kt][q] = f2tf32(w[q] - __uint_as_float(hi));
            }
        }
    }

    {
        const float* src = Gt + (size_t)(tid >> 6) * 32768 + bid * 256 + (tid & 63) * 4;
        cp16(gsm_u32 + tid * 16, src);
        cp_commit();
    }

    const int jl = tid >> 6;
    const int bb = tid & 63;
    float c = 0.f;

    for (int t = 0; t < TT; t++) {
        if (t == 0) {
            for (int idx = tid; idx < 64 * 128; idx += 256) {
                int b = idx >> 7, kq = idx & 127;
                *(float4*)&Hsm[b * HPITCH + kq * 4] = make_float4(0.f, 0.f, 0.f, 0.f);
            }
        } else {
            const float4* hsrc = (const float4*)(hhist + (size_t)(t - 1) * BB * 512);
#pragma unroll
            for (int ii = 0; ii < 32; ii++) {
                int idx = tid + ii * 256;
                int b = idx >> 7, kq = idx & 127;
                cp16(hsm_u32 + (uint32_t)(b * HPITCH + kq * 4) * 4u,
                     hsrc + b * 128 + kq);
            }
        }
        cp_commit();
        if (t + 1 < TT) {
            const float* src = Gt + (size_t)(t + 1) * 131072
                             + (size_t)(tid >> 6) * 32768 + bid * 256 + (tid & 63) * 4;
            cp16(gsm_u32 + (uint32_t)(((t + 1) & 1) * 4096) + tid * 16, src);
        }
        cp_commit();
        cp_wait1();
        __syncthreads();

        float d[8][4];
#pragma unroll
        for (int nt = 0; nt < 8; nt++)
#pragma unroll
            for (int q = 0; q < 4; q++) d[nt][q] = 0.f;

#pragma unroll
        for (int kt = 0; kt < 8; kt++) {
            const int kcol = kb + kt * 8 + ctg;
#pragma unroll
            for (int nt = 0; nt < 8; nt++) {
                const float* hp = Hsm + (nt * 8 + g4id) * HPITCH + kcol;
                float b0f = hp[0];
                float b1f = hp[4];
                uint32_t h0 = f2tf32(b0f);
                uint32_t h1 = f2tf32(b1f);
                uint32_t l0 = f2tf32(b0f - __uint_as_float(h0));
                uint32_t l1 = f2tf32(b1f - __uint_as_float(h1));
                mma_tf32(d[nt], aHi[kt], h0, h1);
                mma_tf32(d[nt], aLo[kt], h0, h1);
                mma_tf32(d[nt], aHi[kt], l0, l1);
            }
        }

        {
            float* rw = Rsm + warp * RWARP;
#pragma unroll
            for (int nt = 0; nt < 8; nt++) {
                int col = nt * 8 + ctg * 2;
                *(float2*)&rw[g4id * RPITCH + col]       = make_float2(d[nt][0], d[nt][1]);
                *(float2*)&rw[(g4id + 8) * RPITCH + col] = make_float2(d[nt][2], d[nt][3]);
            }
        }
        __syncthreads();

        {
            const float* gs = Gsm + (t & 1) * 1024;
            float g4[4];
#pragma unroll
            for (int g = 0; g < 4; g++) {
                int r = g * 4 + jl;
                float s = 0.f;
#pragma unroll
                for (int p = 0; p < 8; p++) s += Rsm[p * RWARP + r * RPITCH + bb];
                g4[g] = s + gs[g * 256 + tid];
            }
            c = sigm(g4[1]) * c + sigm(g4[0]) * tanhf(g4[2]);
            float h = sigm(g4[3]) * tanhf(c);
            Hbuf[bb * 4 + jl] = h;
        }
        __syncthreads();

        if (tid < 64) {
            float4 v = *(float4*)&Hbuf[tid * 4];
            *(float4*)&hhist[(size_t)t * BB * 512 + (size_t)tid * 512 + bid * 4] = v;
            if (clipout) {
                float4 cv;
                cv.x = fminf(fmaxf(v.x, -20.f), 20.f);
                cv.y = fminf(fmaxf(v.y, -20.f), 20.f);
                cv.z = fminf(fmaxf(v.z, -20.f), 20.f);
                cv.w = fminf(fmaxf(v.w, -20.f), 20.f);
                *(float4*)&clipout[((size_t)t * BB + tid) * CATW + bid * 4] = cv;
            }
        }

        if (t + 1 < TT) grid_sync();
    }
}

// ---------------- DNC memory module: 64 blocks x 512 threads ----------------
struct MemSmem {
    float mem[NNq][WWq + 1];
    float link[NNq][NNq + 1];
    float prec[NNq], usage[NNq], ww[NNq];
    float rw[RRq][NNq], rw2[RRq][NNq], fwd[RRq][NNq], bwd[RRq][NNq], rc[RRq][NNq];
    float wc[NNq], u[NNq], su[NNq], pe[NNq], norms[NNq];
    int   rank[NNq];
    float rkeys[RRq][WWq];
    float wkey[WWq], wvec[WWq], erase[WWq];
    float rstr[RRq], fg[RRq], rknorm[RRq];
    float modes[RRq][3];
    float scal[8];
};
#define S_WSTR 0
#define S_AG   1
#define S_WG   2
#define S_KN   3
#define S_SWW  4

__global__ void __launch_bounds__(512) memory_kernel(
    const float* __restrict__ xi_all, float* __restrict__ cat)
{
    extern __shared__ __align__(16) char smraw[];
    MemSmem* s = (MemSmem*)smraw;
    const int b = blockIdx.x, tid = threadIdx.x;

    for (int i = tid; i < (int)(sizeof(MemSmem) / 4); i += 512) ((float*)smraw)[i] = 0.f;
    __syncthreads();

    for (int t = 0; t < TT; t++) {
        const float* xi = xi_all + ((size_t)t * BB + b) * IFACEq;

        // ---- parse interface ----
        if (tid < 256) { int r = tid >> 6, w = tid & 63; s->rkeys[r][w] = tanhf(xi[tid]); }
        if (tid < 64) {
            s->wkey[tid]  = tanhf(xi[260 + tid]);
            s->erase[tid] = sigm (xi[325 + tid]);
            s->wvec[tid]  = tanhf(xi[389 + tid]);
        } else if (tid < 68) s->rstr[tid - 64] = splus(xi[256 + tid - 64]);
        else if (tid < 72)   s->fg[tid - 68]   = sigm (xi[453 + tid - 68]);
        else if (tid == 72)  s->scal[S_WSTR]   = splus(xi[324]);
        else if (tid == 73)  s->scal[S_AG]     = sigm (xi[457]);
        else if (tid == 74)  s->scal[S_WG]     = sigm (xi[458]);
        else if (tid >= 80 && tid < 84) {
            int r = tid - 80;
            float x0 = xi[459 + 3*r], x1 = xi[460 + 3*r], x2 = xi[461 + 3*r];
            float m = fmaxf(x0, fmaxf(x1, x2));
            float e0 = expf(x0 - m), e1 = expf(x1 - m), e2 = expf(x2 - m);
            float inv = 1.f / (e0 + e1 + e2);
            s->modes[r][0] = e0*inv; s->modes[r][1] = e1*inv; s->modes[r][2] = e2*inv;
        }
        __syncthreads();

        // ---- usage (old ww/rw), old-mem norms (split rows over 256 threads), key norms ----
        if (tid < 128) {
            float us = s->usage[tid] + (1.f - s->usage[tid]) * s->ww[tid];
            float ret = 1.f;
#pragma unroll
            for (int r = 0; r < RRq; r++) ret *= (1.f - s->fg[r] * s->rw[r][tid]);
            s->usage[tid] = us * ret;
        } else if (tid < 160) {
            int l = tid - 128;
            float pq = s->wkey[l]*s->wkey[l] + s->wkey[l+32]*s->wkey[l+32];
            pq = warp_sum(pq);
            if (l == 0) s->scal[S_KN] = sqrtf(pq);
        } else if (tid < 164) {
            int r = tid - 160; float ss = 0.f;
            for (int w = 0; w < WWq; w++) ss += s->rkeys[r][w]*s->rkeys[r][w];
            s->rknorm[r] = sqrtf(ss);
        } else if (tid >= 256) {
            // norms: 256 threads, 2 per row (halves of 64)
            int q = tid - 256;
            int n = q >> 1, half = (q & 1) * 32;
            float ss = 0.f;
#pragma unroll 8
            for (int w = 0; w < 32; w++) { float v = s->mem[n][half + w]; ss += v * v; }
            ss += __shfl_xor_sync(0xffffffffu, ss, 1);
            if ((q & 1) == 0) s->norms[n] = ss;   // store sum of squares; sqrt below
        }
        __syncthreads();

        // ---- write content weights (old mem): 2 threads/row ----
        if (tid < 256) {
            int n = tid >> 1, half = (tid & 1) * 32;
            float d = 0.f;
#pragma unroll 8
            for (int w = 0; w < 32; w++) d += s->wkey[half + w] * s->mem[n][half + w];
            d += __shfl_xor_sync(0xffffffffu, d, 1);
            if ((tid & 1) == 0) {
                float nr = sqrtf(s->norms[n]);
                s->norms[n] = nr;
                s->wc[n] = d / ((nr + EPSq) * (s->scal[S_KN] + EPSq)) * s->scal[S_WSTR];
            }
        }
        __syncthreads();
        if (tid < 32) {
            float v0 = s->wc[tid], v1 = s->wc[tid+32], v2 = s->wc[tid+64], v3 = s->wc[tid+96];
            float mx = warp_max(fmaxf(fmaxf(v0, v1), fmaxf(v2, v3)));
            v0 = expf(v0-mx); v1 = expf(v1-mx); v2 = expf(v2-mx); v3 = expf(v3-mx);
            float inv = 1.f / warp_sum(v0 + v1 + v2 + v3);
            s->wc[tid] = v0*inv; s->wc[tid+32] = v1*inv; s->wc[tid+64] = v2*inv; s->wc[tid+96] = v3*inv;
        }
        __syncthreads();

        // ---- allocation: stable rank + cumprod scan ----
        if (tid < 128) s->u[tid] = DELTAq + (1.f - DELTAq) * s->usage[tid];
        __syncthreads();
        if (tid < 128) {
            float ui = s->u[tid]; int rk = 0;
            for (int j = 0; j < 128; j++) {
                float uj = s->u[j];
                rk += (uj < ui) || (uj == ui && j < tid);
            }
            s->rank[tid] = rk;
            s->su[rk] = ui;
        }
        __syncthreads();
        if (tid < 128) s->pe[tid] = s->su[tid];
        __syncthreads();
        for (int d = 1; d < 128; d <<= 1) {
            float v = 1.f;
            if (tid < 128 && tid >= d) v = s->pe[tid - d];
            __syncthreads();
            if (tid < 128 && tid >= d) s->pe[tid] *= v;
            __syncthreads();
        }
        if (tid < 128) {
            int rk = s->rank[tid];
            float excl = rk ? s->pe[rk - 1] : 1.f;
            float alloc = (1.f - s->u[tid]) * excl;
            float ag = s->scal[S_AG], wg = s->scal[S_WG];
            s->ww[tid] = wg * (ag * alloc + (1.f - ag) * s->wc[tid]);
        }
        __syncthreads();
        if (tid < 32) {
            float v = s->ww[tid] + s->ww[tid+32] + s->ww[tid+64] + s->ww[tid+96];
            v = warp_sum(v);
            if (tid == 0) s->scal[S_SWW] = v;
        }
        __syncthreads();

        // ---- mem write (8 row-groups x 16) + link update (4 j-groups x 32, swizzled) ----
        {
            int w = tid & 63, ng = tid >> 6;     // ng 0..7
            for (int i = 0; i < 16; i++) {
                int n = ng * 16 + i;
                float wwn = s->ww[n];
                s->mem[n][w] = s->mem[n][w] * (1.f - wwn * s->erase[w]) + wwn * s->wvec[w];
            }
        }
        {
            int i = tid >> 2, grp = tid & 3;
            float wwi = s->ww[i];
            for (int jj = 0; jj < 32; jj++) {
                int j = grp * 32 + ((jj + grp * 8) & 31);
                float l = (1.f - wwi - s->ww[j]) * s->link[i][j] + wwi * s->prec[j];
                s->link[i][j] = (i == j) ? 0.f : l;
            }
        }
        __syncthreads();

        // ---- prec update + new-mem norms (2 threads/row) ----
        if (tid < 128) {
            s->prec[tid] = (1.f - s->scal[S_SWW]) * s->prec[tid] + s->ww[tid];
        } else if (tid >= 256) {
            int q = tid - 256;
            int n = q >> 1, half = (q & 1) * 32;
            float ss = 0.f;
#pragma unroll 8
            for (int w = 0; w < 32; w++) { float v = s->mem[n][half + w]; ss += v * v; }
            ss += __shfl_xor_sync(0xffffffffu, ss, 1);
            if ((q & 1) == 0) s->norms[n] = sqrtf(ss);
        }
        __syncthreads();

        // ---- read content (new mem): 512 items, 1/thread ----
        {
            int r = tid >> 7, n = tid & 127;
            float d = 0.f;
#pragma unroll 8
            for (int w = 0; w < WWq; w++) d += s->rkeys[r][w] * s->mem[n][w];
            s->rc[r][n] = d / ((s->norms[n] + EPSq) * (s->rknorm[r] + EPSq)) * s->rstr[r];
        }
        __syncthreads();
        if (tid < 128) {
            int r = tid >> 5, l = tid & 31;
            float v0 = s->rc[r][l], v1 = s->rc[r][l+32], v2 = s->rc[r][l+64], v3 = s->rc[r][l+96];
            float mx = warp_max(fmaxf(fmaxf(v0, v1), fmaxf(v2, v3)));
            v0 = expf(v0-mx); v1 = expf(v1-mx); v2 = expf(v2-mx); v3 = expf(v3-mx);
            float inv = 1.f / warp_sum(v0 + v1 + v2 + v3);
            s->rc[r][l] = v0*inv; s->rc[r][l+32] = v1*inv; s->rc[r][l+64] = v2*inv; s->rc[r][l+96] = v3*inv;
        }
        __syncthreads();

        // ---- fwd/bwd: 512 items, 1/thread ----
        {
            int r = tid >> 7, n = tid & 127;
            float f = 0.f, bw = 0.f;
#pragma unroll 4
            for (int m = 0; m < 128; m++) {
                float rv = s->rw[r][m];
                f  += rv * s->link[n][m];
                bw += rv * s->link[m][n];
            }
            s->fwd[r][n] = f; s->bwd[r][n] = bw;
        }
        __syncthreads();
        {
            int r = tid >> 7, n = tid & 127;
            s->rw2[r][n] = s->modes[r][0]*s->bwd[r][n] + s->modes[r][1]*s->rc[r][n] + s->modes[r][2]*s->fwd[r][n];
        }
        __syncthreads();
        { int r = tid >> 7, n = tid & 127; s->rw[r][n] = s->rw2[r][n]; }
        __syncthreads();

        // ---- read vectors -> cat[512:768] (tid<256) ----
        if (tid < 256) {
            int r = tid >> 6, w = tid & 63;
            float acc = 0.f;
#pragma unroll 4
            for (int n = 0; n < 128; n++) acc += s->rw[r][n] * s->mem[n][w];
            cat[((size_t)t * BB + b) * CATW + 512 + tid] = acc;
        }
        __syncthreads();
    }
}

__global__ void gather_hid(float* __restrict__ out, const int* __restrict__ lens) {
    int b = blockIdx.x, i = threadIdx.x;
    int t = lens[b] - 1;
    out[(size_t)TT * BB * IDIMq + (size_t)b * IDIMq + i] = out[((size_t)t * BB + b) * IDIMq + i];
}

extern "C" void kernel_launch(void* const* d_in, const int* in_sizes, int n_in,
                              void* d_out, int out_size) {
    const float* embs = (const float*)d_in[0];
    const int*   lens = (const int*)  d_in[1];
    const float* Wih0 = (const float*)d_in[2];
    const float* Whh0 = (const float*)d_in[3];
    const float* bih0 = (const float*)d_in[4];
    const float* bhh0 = (const float*)d_in[5];
    const float* Wih1 = (const float*)d_in[6];
    const float* Whh1 = (const float*)d_in[7];
    const float* bih1 = (const float*)d_in[8];
    const float* bhh1 = (const float*)d_in[9];
    const float* Wxi  = (const float*)d_in[10];
    const float* bxi  = (const float*)d_in[11];
    const float* Wout = (const float*)d_in[12];
    const float* bout = (const float*)d_in[13];
    float* out = (float*)d_out;

    float *G, *h0, *h1, *cat, *xi;
    cudaGetSymbolAddress((void**)&G,   g_G);
    cudaGetSymbolAddress((void**)&h0,  g_h0);
    cudaGetSymbolAddress((void**)&h1,  g_h1);
    cudaGetSymbolAddress((void**)&cat, g_cat);
    cudaGetSymbolAddress((void**)&xi,  g_xi);

    cudaFuncSetAttribute(memory_kernel, cudaFuncAttributeMaxDynamicSharedMemorySize,
                         (int)sizeof(MemSmem));
    cudaFuncSetAttribute(lstm_persist, cudaFuncAttributeMaxDynamicSharedMemorySize,
                         SM_FLOATS * 4);
    cudaFuncSetAttribute(sgemm_tf32_tg, cudaFuncAttributeMaxDynamicSharedMemorySize,
                         GSM_FLOATS * 4);
    cudaFuncSetAttribute(sgemm_tf32_pl, cudaFuncAttributeMaxDynamicSharedMemorySize,
                         GSM_FLOATS * 4);

    // Gpre0^T = (embs @ Wih0[:, :256]^T + bih0 + bhh0) transposed  [t][2048][64]
    sgemm_tf32_tg<<<dim3(16, 64), 256, GSM_FLOATS * 4>>>(embs, IDIMq, Wih0, CDIMq, G, bih0, bhh0, IDIMq);

    // layer 0: all 128 steps, one persistent kernel
    lstm_persist<<<NBLK, 256, SM_FLOATS * 4>>>(G, Whh0, h0, nullptr);

    // Gpre1^T = (h0 @ Wih1^T + bih1 + bhh1) transposed
    sgemm_tf32_tg<<<dim3(16, 64), 256, GSM_FLOATS * 4>>>(h0, CDIMq, Wih1, CDIMq, G, bih1, bhh1, CDIMq);

    // layer 1: all 128 steps (also writes clip(h1) into cat)
    lstm_persist<<<NBLK, 256, SM_FLOATS * 4>>>(G, Whh1, h1, cat);

    // xi = clip(h1) @ Wxi^T + bxi   (tf32, ragged N)
    sgemm_tf32_pl<<<dim3(4, 64), 256, GSM_FLOATS * 4>>>(cat, CATW, Wxi, CDIMq, xi, IFACEq, bxi, IFACEq, CDIMq);

    memory_kernel<<<64, 512, sizeof(MemSmem)>>>(xi, cat);

    // y = cat @ Wout^T + bout   (tf32)
    sgemm_tf32_pl<<<dim3(2, 64), 256, GSM_FLOATS * 4>>>(cat, CATW, Wout, CATW, out, IDIMq, bout, IDIMq, CATW);

    gather_hid<<<64, 256>>>(out, lens);
}